// round 1
// baseline (speedup 1.0000x reference)
#include <cuda_runtime.h>
#include <cuda_bf16.h>
#include <math.h>

#define BB   2
#define NN   2048
#define DIM  512
#define HH   8
#define DD   64
#define BN   (BB*NN)    // 4096
#define BHD  (BB*HH)    // 16

// Scratch (allocation-free): q,k,v in [b,h,n,d], attention output in [b,n,h*d]
__device__ float g_q[BHD*NN*DD];
__device__ float g_k[BHD*NN*DD];
__device__ float g_v[BHD*NN*DD];
__device__ float g_att[BN*DIM];

// ---------------------------------------------------------------------------
// Kernel 1: QKV GEMM.  C[4096,1536] = x[4096,512] @ W_in[512,1536] + b_in
// 128x128 tile, 16x16 threads, 8x8 micro-tile. Epilogue scatters to q/k/v.
// ---------------------------------------------------------------------------
__global__ __launch_bounds__(256, 2) void qkv_gemm_kernel(
    const float* __restrict__ x, const float* __restrict__ W,
    const float* __restrict__ bin)
{
    __shared__ float AsT[16][132];   // k-major A tile (transposed)
    __shared__ float Bs[16][132];

    const int tid = threadIdx.x;
    const int tx = tid & 15, ty = tid >> 4;
    const int row0 = blockIdx.y * 128;
    const int col0 = blockIdx.x * 128;

    float acc[8][8];
#pragma unroll
    for (int i = 0; i < 8; i++)
#pragma unroll
        for (int j = 0; j < 8; j++) acc[i][j] = 0.f;

    for (int k0 = 0; k0 < 512; k0 += 16) {
#pragma unroll
        for (int s = 0; s < 2; s++) {
            int idx = tid + s * 256;
            // A: 128 rows x 16 k  (float4 per thread, transpose-store)
            int r = idx >> 2, c4 = idx & 3;
            float4 va = *(const float4*)(x + (size_t)(row0 + r) * 512 + k0 + c4 * 4);
            AsT[c4 * 4 + 0][r] = va.x;
            AsT[c4 * 4 + 1][r] = va.y;
            AsT[c4 * 4 + 2][r] = va.z;
            AsT[c4 * 4 + 3][r] = va.w;
            // B: 16 k x 128 cols
            int kr = idx >> 5, cc = idx & 31;
            *(float4*)&Bs[kr][cc * 4] =
                *(const float4*)(W + (size_t)(k0 + kr) * 1536 + col0 + cc * 4);
        }
        __syncthreads();
#pragma unroll
        for (int kk = 0; kk < 16; kk++) {
            float4 a0 = *(float4*)&AsT[kk][ty * 8];
            float4 a1 = *(float4*)&AsT[kk][ty * 8 + 4];
            float4 b0 = *(float4*)&Bs[kk][tx * 4];
            float4 b1 = *(float4*)&Bs[kk][64 + tx * 4];
            float a[8] = {a0.x, a0.y, a0.z, a0.w, a1.x, a1.y, a1.z, a1.w};
            float b[8] = {b0.x, b0.y, b0.z, b0.w, b1.x, b1.y, b1.z, b1.w};
#pragma unroll
            for (int i = 0; i < 8; i++)
#pragma unroll
                for (int j = 0; j < 8; j++) acc[i][j] += a[i] * b[j];
        }
        __syncthreads();
    }

    // Epilogue: c = col0 + half*64 + tx*4 + jj ; scatter with bias
#pragma unroll
    for (int i = 0; i < 8; i++) {
        int m  = row0 + ty * 8 + i;
        int bi = m >> 11;          // / 2048
        int ni = m & 2047;
#pragma unroll
        for (int half = 0; half < 2; half++) {
            int c = col0 + half * 64 + tx * 4;
            float4 bv = *(const float4*)(bin + c);
            float4 r;
            r.x = acc[i][half * 4 + 0] + bv.x;
            r.y = acc[i][half * 4 + 1] + bv.y;
            r.z = acc[i][half * 4 + 2] + bv.z;
            r.w = acc[i][half * 4 + 3] + bv.w;
            int three = c >> 9;            // uniform per (block, half)
            int head  = (c >> 6) & 7;
            float* dst = (three == 0) ? g_q : (three == 1) ? g_k : g_v;
            size_t off = (((size_t)bi * HH + head) * NN + ni) * DD + (c & 63);
            *(float4*)&dst[off] = r;
        }
    }
}

// ---------------------------------------------------------------------------
// Kernel 2: per-head LayerNorm on q and k rows (d=64). One warp per row.
// ---------------------------------------------------------------------------
__global__ void ln_qk_kernel(const float* __restrict__ qn_w, const float* __restrict__ qn_b,
                             const float* __restrict__ kn_w, const float* __restrict__ kn_b)
{
    const int ROWS = BHD * NN;      // 32768 per tensor
    int gid = blockIdx.x * 8 + (threadIdx.x >> 5);
    int lane = threadIdx.x & 31;
    if (gid >= 2 * ROWS) return;
    bool isq = gid < ROWS;
    int r = isq ? gid : gid - ROWS;
    float* buf = isq ? g_q : g_k;
    const float* w = isq ? qn_w : kn_w;
    const float* bb = isq ? qn_b : kn_b;

    float x0 = buf[(size_t)r * 64 + lane];
    float x1 = buf[(size_t)r * 64 + 32 + lane];
    float s = x0 + x1;
#pragma unroll
    for (int off = 16; off >= 1; off >>= 1) s += __shfl_xor_sync(0xffffffffu, s, off);
    float mu = s * (1.0f / 64.0f);
    float d0 = x0 - mu, d1 = x1 - mu;
    float v = d0 * d0 + d1 * d1;
#pragma unroll
    for (int off = 16; off >= 1; off >>= 1) v += __shfl_xor_sync(0xffffffffu, v, off);
    float inv = rsqrtf(v * (1.0f / 64.0f) + 1e-5f);
    buf[(size_t)r * 64 + lane]      = d0 * inv * w[lane] + bb[lane];
    buf[(size_t)r * 64 + 32 + lane] = d1 * inv * w[lane + 32] + bb[lane + 32];
}

// ---------------------------------------------------------------------------
// Kernel 3: flash attention with positional bias.
// Grid (16 q-tiles, 16 bh). 128-query x 64-key tiles, 256 threads, 8x4 micro.
// XOR swizzle at float4 granularity: phys_group = g ^ ((row>>2)&15).
// ---------------------------------------------------------------------------
#define ATTN_SMEM_FLOATS (8192 + 4096 + 4096 + 8192 + 256 + 128)
#define ATTN_SMEM_BYTES  (ATTN_SMEM_FLOATS * 4)

__global__ __launch_bounds__(256, 2) void attn_kernel(const float* __restrict__ pos)
{
    extern __shared__ float sm[];
    float* Qs = sm;               // [128][64] swizzled
    float* Ks = Qs + 8192;        // [64][64]  swizzled
    float* Vs = Ks + 4096;        // [64][64]  row-major
    float* Ps = Vs + 4096;        // [64][128] swizzled over row dim
    float* pq = Ps + 8192;        // [128][2]
    float* pk = pq + 256;         // [64][2]

    const int tid = threadIdx.x;
    const int tx = tid & 15, ty = tid >> 4;
    const int q0 = blockIdx.x * 128;
    const int bh = blockIdx.y;
    const int bi = bh >> 3, head = bh & 7;

    const float* qb = g_q + (size_t)bh * NN * DD;
    const float* kb = g_k + (size_t)bh * NN * DD;
    const float* vb = g_v + (size_t)bh * NN * DD;

    // Load Q tile (swizzled) + query positions
#pragma unroll
    for (int s = 0; s < 8; s++) {
        int idx = tid + 256 * s;
        int cf = idx & 15, j = idx >> 4;
        float4 v = *(const float4*)(qb + (size_t)(q0 + j) * 64 + cf * 4);
        int pg = cf ^ ((j >> 2) & 15);
        *(float4*)&Qs[j * 64 + pg * 4] = v;
    }
    if (tid < 128)
        *(float2*)&pq[tid * 2] = *(const float2*)(pos + (size_t)(q0 + tid) * 2);

    float o[8][4];
    float mrow[8], lrow[8];
#pragma unroll
    for (int i = 0; i < 8; i++) {
        mrow[i] = -1e30f; lrow[i] = 0.f;
#pragma unroll
        for (int j = 0; j < 4; j++) o[i][j] = 0.f;
    }

    // query positions in regs
    float pqx[8], pqy[8];
    __syncthreads();   // Qs + pq visible
#pragma unroll
    for (int i = 0; i < 8; i++) {
        pqx[i] = pq[(ty * 8 + i) * 2 + 0];
        pqy[i] = pq[(ty * 8 + i) * 2 + 1];
    }

    for (int kt = 0; kt < 32; kt++) {
        const int k0 = kt * 64;
        __syncthreads();   // prior PV reads of Ks/Vs/Ps done
        // load K (swizzled), V (row-major), key positions
#pragma unroll
        for (int s = 0; s < 4; s++) {
            int idx = tid + 256 * s;
            int cf = idx & 15, j = idx >> 4;
            float4 kv4 = *(const float4*)(kb + (size_t)(k0 + j) * 64 + cf * 4);
            int pg = cf ^ ((j >> 2) & 15);
            *(float4*)&Ks[j * 64 + pg * 4] = kv4;
            float4 vv4 = *(const float4*)(vb + (size_t)(k0 + j) * 64 + cf * 4);
            *(float4*)&Vs[j * 64 + cf * 4] = vv4;
        }
        if (tid < 64)
            *(float2*)&pk[tid * 2] = *(const float2*)(pos + (size_t)(k0 + tid) * 2);
        __syncthreads();

        // S = Q K^T (dot form over swizzled float4 groups)
        float sacc[8][4];
#pragma unroll
        for (int i = 0; i < 8; i++)
#pragma unroll
            for (int j = 0; j < 4; j++) sacc[i][j] = 0.f;

#pragma unroll
        for (int g = 0; g < 16; g++) {
            float4 kv[4];
#pragma unroll
            for (int jj = 0; jj < 4; jj++) {
                int r = tx * 4 + jj;
                kv[jj] = *(const float4*)&Ks[r * 64 + ((g ^ tx) & 15) * 4];
            }
#pragma unroll
            for (int i = 0; i < 8; i++) {
                int row = ty * 8 + i;
                float4 qv = *(const float4*)&Qs[row * 64 + ((g ^ ((row >> 2) & 15)) & 15) * 4];
#pragma unroll
                for (int jj = 0; jj < 4; jj++) {
                    sacc[i][jj] += qv.x * kv[jj].x + qv.y * kv[jj].y
                                 + qv.z * kv[jj].z + qv.w * kv[jj].w;
                }
            }
        }

        // key positions for this tile
        float pkx[4], pky[4];
#pragma unroll
        for (int jj = 0; jj < 4; jj++) {
            pkx[jj] = pk[(tx * 4 + jj) * 2 + 0];
            pky[jj] = pk[(tx * 4 + jj) * 2 + 1];
        }

        // scale + bias + online softmax (rows shared across 16-lane groups)
#pragma unroll
        for (int i = 0; i < 8; i++) {
            float rmax = -1e30f;
#pragma unroll
            for (int jj = 0; jj < 4; jj++) {
                float dx = fabsf(pqx[i] - pkx[jj]); dx += 0.5f; dx -= floorf(dx); dx -= 0.5f;
                float dy = fabsf(pqy[i] - pky[jj]); dy += 0.5f; dy -= floorf(dy); dy -= 0.5f;
                float sv = sacc[i][jj] * 0.125f - (dx * dx + dy * dy);
                sacc[i][jj] = sv;
                rmax = fmaxf(rmax, sv);
            }
#pragma unroll
            for (int off = 8; off >= 1; off >>= 1)
                rmax = fmaxf(rmax, __shfl_xor_sync(0xffffffffu, rmax, off));
            float mnew = fmaxf(mrow[i], rmax);
            float corr = __expf(mrow[i] - mnew);
            float rsum = 0.f;
#pragma unroll
            for (int jj = 0; jj < 4; jj++) {
                float p = __expf(sacc[i][jj] - mnew);
                sacc[i][jj] = p;
                rsum += p;
            }
#pragma unroll
            for (int off = 8; off >= 1; off >>= 1)
                rsum += __shfl_xor_sync(0xffffffffu, rsum, off);
            lrow[i] = lrow[i] * corr + rsum;
            mrow[i] = mnew;
#pragma unroll
            for (int jj = 0; jj < 4; jj++) o[i][jj] *= corr;
        }

        // store P transposed (swizzled): Ps[kk][row]
#pragma unroll
        for (int jj = 0; jj < 4; jj++) {
            int kk = tx * 4 + jj;
#pragma unroll
            for (int h = 0; h < 2; h++) {
                int pg = (2 * ty + h) ^ tx;    // (kk>>2)&15 == tx
                float4 pv = make_float4(sacc[4 * h + 0][jj], sacc[4 * h + 1][jj],
                                        sacc[4 * h + 2][jj], sacc[4 * h + 3][jj]);
                *(float4*)&Ps[kk * 128 + pg * 4] = pv;
            }
        }
        __syncthreads();

        // O += P @ V
#pragma unroll
        for (int kk = 0; kk < 64; kk++) {
            float4 vv = *(const float4*)&Vs[kk * 64 + tx * 4];
            int swk = (kk >> 2) & 15;
            float4 p0 = *(const float4*)&Ps[kk * 128 + ((2 * ty) ^ swk) * 4];
            float4 p1 = *(const float4*)&Ps[kk * 128 + ((2 * ty + 1) ^ swk) * 4];
            float pr[8] = {p0.x, p0.y, p0.z, p0.w, p1.x, p1.y, p1.z, p1.w};
            float vr[4] = {vv.x, vv.y, vv.z, vv.w};
#pragma unroll
            for (int i = 0; i < 8; i++)
#pragma unroll
                for (int jj = 0; jj < 4; jj++) o[i][jj] += pr[i] * vr[jj];
        }
    }

    // final normalize + write [b, n, h, d]
#pragma unroll
    for (int i = 0; i < 8; i++) {
        float inv = 1.0f / lrow[i];
        int row = q0 + ty * 8 + i;
        float4 r = make_float4(o[i][0] * inv, o[i][1] * inv, o[i][2] * inv, o[i][3] * inv);
        *(float4*)&g_att[((size_t)bi * NN + row) * DIM + head * 64 + tx * 4] = r;
    }
}

// ---------------------------------------------------------------------------
// Kernel 4: output GEMM.  out[4096,512] = g_att @ W_out[512,512] + b_out
// ---------------------------------------------------------------------------
__global__ __launch_bounds__(256, 2) void out_gemm_kernel(
    const float* __restrict__ W, const float* __restrict__ bout, float* __restrict__ out)
{
    __shared__ float AsT[16][132];
    __shared__ float Bs[16][132];

    const int tid = threadIdx.x;
    const int tx = tid & 15, ty = tid >> 4;
    const int row0 = blockIdx.y * 128;
    const int col0 = blockIdx.x * 128;

    float acc[8][8];
#pragma unroll
    for (int i = 0; i < 8; i++)
#pragma unroll
        for (int j = 0; j < 8; j++) acc[i][j] = 0.f;

    for (int k0 = 0; k0 < 512; k0 += 16) {
#pragma unroll
        for (int s = 0; s < 2; s++) {
            int idx = tid + s * 256;
            int r = idx >> 2, c4 = idx & 3;
            float4 va = *(const float4*)(g_att + (size_t)(row0 + r) * 512 + k0 + c4 * 4);
            AsT[c4 * 4 + 0][r] = va.x;
            AsT[c4 * 4 + 1][r] = va.y;
            AsT[c4 * 4 + 2][r] = va.z;
            AsT[c4 * 4 + 3][r] = va.w;
            int kr = idx >> 5, cc = idx & 31;
            *(float4*)&Bs[kr][cc * 4] =
                *(const float4*)(W + (size_t)(k0 + kr) * 512 + col0 + cc * 4);
        }
        __syncthreads();
#pragma unroll
        for (int kk = 0; kk < 16; kk++) {
            float4 a0 = *(float4*)&AsT[kk][ty * 8];
            float4 a1 = *(float4*)&AsT[kk][ty * 8 + 4];
            float4 b0 = *(float4*)&Bs[kk][tx * 4];
            float4 b1 = *(float4*)&Bs[kk][64 + tx * 4];
            float a[8] = {a0.x, a0.y, a0.z, a0.w, a1.x, a1.y, a1.z, a1.w};
            float b[8] = {b0.x, b0.y, b0.z, b0.w, b1.x, b1.y, b1.z, b1.w};
#pragma unroll
            for (int i = 0; i < 8; i++)
#pragma unroll
                for (int j = 0; j < 8; j++) acc[i][j] += a[i] * b[j];
        }
        __syncthreads();
    }

#pragma unroll
    for (int i = 0; i < 8; i++) {
        int m = row0 + ty * 8 + i;
#pragma unroll
        for (int half = 0; half < 2; half++) {
            int c = col0 + half * 64 + tx * 4;
            float4 bv = *(const float4*)(bout + c);
            float4 r;
            r.x = acc[i][half * 4 + 0] + bv.x;
            r.y = acc[i][half * 4 + 1] + bv.y;
            r.z = acc[i][half * 4 + 2] + bv.z;
            r.w = acc[i][half * 4 + 3] + bv.w;
            *(float4*)&out[(size_t)m * 512 + c] = r;
        }
    }
}

// ---------------------------------------------------------------------------
extern "C" void kernel_launch(void* const* d_in, const int* in_sizes, int n_in,
                              void* d_out, int out_size)
{
    const float* x    = (const float*)d_in[0];
    const float* pos  = (const float*)d_in[1];
    const float* W_in = (const float*)d_in[2];
    const float* b_in = (const float*)d_in[3];
    const float* qn_w = (const float*)d_in[4];
    const float* qn_b = (const float*)d_in[5];
    const float* kn_w = (const float*)d_in[6];
    const float* kn_b = (const float*)d_in[7];
    const float* W_out= (const float*)d_in[8];
    const float* b_out= (const float*)d_in[9];
    float* out = (float*)d_out;

    qkv_gemm_kernel<<<dim3(12, 32), 256>>>(x, W_in, b_in);
    ln_qk_kernel<<<(2 * BHD * NN) / 8, 256>>>(qn_w, qn_b, kn_w, kn_b);

    cudaFuncSetAttribute(attn_kernel, cudaFuncAttributeMaxDynamicSharedMemorySize,
                         ATTN_SMEM_BYTES);
    attn_kernel<<<dim3(16, 16), 256, ATTN_SMEM_BYTES>>>(pos);

    out_gemm_kernel<<<dim3(4, 32), 256>>>(W_out, b_out, out);
}

// round 2
// speedup vs baseline: 1.1576x; 1.1576x over previous
#include <cuda_runtime.h>
#include <cuda_bf16.h>
#include <math.h>

#define BB   2
#define NN   2048
#define DIM  512
#define HH   8
#define DD   64
#define BN   (BB*NN)    // 4096
#define BHD  (BB*HH)    // 16

// Scratch (allocation-free)
__device__ float g_q[BHD*NN*DD];
__device__ float g_k[BHD*NN*DD];
__device__ float g_v[BHD*NN*DD];
__device__ float g_att[BN*DIM];

// ---------------------------------------------------------------------------
// packed f32x2 helpers (SASS FFMA2 path — only reachable via PTX)
// ---------------------------------------------------------------------------
typedef unsigned long long u64;

__device__ __forceinline__ u64 ffma2(u64 a, u64 b, u64 c) {
    u64 d;
    asm("fma.rn.f32x2 %0, %1, %2, %3;" : "=l"(d) : "l"(a), "l"(b), "l"(c));
    return d;
}
__device__ __forceinline__ u64 fmul2(u64 a, u64 b) {
    u64 d;
    asm("mul.rn.f32x2 %0, %1, %2;" : "=l"(d) : "l"(a), "l"(b));
    return d;
}
__device__ __forceinline__ u64 pack2(float x, float y) {
    u64 r;
    asm("mov.b64 %0, {%1, %2};" : "=l"(r) : "f"(x), "f"(y));
    return r;
}
__device__ __forceinline__ float2 unpack2(u64 v) {
    float2 r;
    asm("mov.b64 {%0, %1}, %2;" : "=f"(r.x), "=f"(r.y) : "l"(v));
    return r;
}

// ---------------------------------------------------------------------------
// Kernel 1: QKV GEMM.  C[4096,1536] = x[4096,512] @ W_in[512,1536] + b_in
// 128x128 tile, 256 threads, 8x8 micro-tile, FFMA2 inner loop.
// ---------------------------------------------------------------------------
__global__ __launch_bounds__(256, 1) void qkv_gemm_kernel(
    const float* __restrict__ x, const float* __restrict__ W,
    const float* __restrict__ bin)
{
    __shared__ float AsT[16][132];
    __shared__ float Bs[16][132];

    const int tid = threadIdx.x;
    const int tx = tid & 15, ty = tid >> 4;
    const int row0 = blockIdx.y * 128;
    const int col0 = blockIdx.x * 128;

    u64 acc2[8][4];
#pragma unroll
    for (int i = 0; i < 8; i++)
#pragma unroll
        for (int j = 0; j < 4; j++) acc2[i][j] = 0ull;

    for (int k0 = 0; k0 < 512; k0 += 16) {
#pragma unroll
        for (int s = 0; s < 2; s++) {
            int idx = tid + s * 256;
            int r = idx >> 2, c4 = idx & 3;
            float4 va = *(const float4*)(x + (size_t)(row0 + r) * 512 + k0 + c4 * 4);
            AsT[c4 * 4 + 0][r] = va.x;
            AsT[c4 * 4 + 1][r] = va.y;
            AsT[c4 * 4 + 2][r] = va.z;
            AsT[c4 * 4 + 3][r] = va.w;
            int kr = idx >> 5, cc = idx & 31;
            *(float4*)&Bs[kr][cc * 4] =
                *(const float4*)(W + (size_t)(k0 + kr) * 1536 + col0 + cc * 4);
        }
        __syncthreads();
#pragma unroll
        for (int kk = 0; kk < 16; kk++) {
            float4 a0 = *(float4*)&AsT[kk][ty * 8];
            float4 a1 = *(float4*)&AsT[kk][ty * 8 + 4];
            ulonglong2 b0 = *(ulonglong2*)&Bs[kk][tx * 4];
            ulonglong2 b1 = *(ulonglong2*)&Bs[kk][64 + tx * 4];
            float a[8] = {a0.x, a0.y, a0.z, a0.w, a1.x, a1.y, a1.z, a1.w};
#pragma unroll
            for (int i = 0; i < 8; i++) {
                u64 ad = pack2(a[i], a[i]);
                acc2[i][0] = ffma2(ad, b0.x, acc2[i][0]);
                acc2[i][1] = ffma2(ad, b0.y, acc2[i][1]);
                acc2[i][2] = ffma2(ad, b1.x, acc2[i][2]);
                acc2[i][3] = ffma2(ad, b1.y, acc2[i][3]);
            }
        }
        __syncthreads();
    }

#pragma unroll
    for (int i = 0; i < 8; i++) {
        int m  = row0 + ty * 8 + i;
        int bi = m >> 11;
        int ni = m & 2047;
#pragma unroll
        for (int half = 0; half < 2; half++) {
            int c = col0 + half * 64 + tx * 4;
            float4 bv = *(const float4*)(bin + c);
            float2 p0 = unpack2(acc2[i][half * 2 + 0]);
            float2 p1 = unpack2(acc2[i][half * 2 + 1]);
            float4 r;
            r.x = p0.x + bv.x;
            r.y = p0.y + bv.y;
            r.z = p1.x + bv.z;
            r.w = p1.y + bv.w;
            int three = c >> 9;
            int head  = (c >> 6) & 7;
            float* dst = (three == 0) ? g_q : (three == 1) ? g_k : g_v;
            size_t off = (((size_t)bi * HH + head) * NN + ni) * DD + (c & 63);
            *(float4*)&dst[off] = r;
        }
    }
}

// ---------------------------------------------------------------------------
// Kernel 2: per-head LayerNorm on q and k rows (d=64). One warp per row.
// ---------------------------------------------------------------------------
__global__ void ln_qk_kernel(const float* __restrict__ qn_w, const float* __restrict__ qn_b,
                             const float* __restrict__ kn_w, const float* __restrict__ kn_b)
{
    const int ROWS = BHD * NN;
    int gid = blockIdx.x * 8 + (threadIdx.x >> 5);
    int lane = threadIdx.x & 31;
    if (gid >= 2 * ROWS) return;
    bool isq = gid < ROWS;
    int r = isq ? gid : gid - ROWS;
    float* buf = isq ? g_q : g_k;
    const float* w = isq ? qn_w : kn_w;
    const float* bb = isq ? qn_b : kn_b;

    float x0 = buf[(size_t)r * 64 + lane];
    float x1 = buf[(size_t)r * 64 + 32 + lane];
    float s = x0 + x1;
#pragma unroll
    for (int off = 16; off >= 1; off >>= 1) s += __shfl_xor_sync(0xffffffffu, s, off);
    float mu = s * (1.0f / 64.0f);
    float d0 = x0 - mu, d1 = x1 - mu;
    float v = d0 * d0 + d1 * d1;
#pragma unroll
    for (int off = 16; off >= 1; off >>= 1) v += __shfl_xor_sync(0xffffffffu, v, off);
    float inv = rsqrtf(v * (1.0f / 64.0f) + 1e-5f);
    buf[(size_t)r * 64 + lane]      = d0 * inv * w[lane] + bb[lane];
    buf[(size_t)r * 64 + 32 + lane] = d1 * inv * w[lane + 32] + bb[lane + 32];
}

// ---------------------------------------------------------------------------
// Kernel 3: flash attention with positional bias (FFMA2 inner loops).
// Grid (16 q-tiles, 16 bh). 128q x 64k tiles, 256 threads, 8x4 micro.
// ---------------------------------------------------------------------------
#define ATTN_SMEM_FLOATS (8192 + 4096 + 4096 + 8192 + 256 + 128)
#define ATTN_SMEM_BYTES  (ATTN_SMEM_FLOATS * 4)

__global__ __launch_bounds__(256, 1) void attn_kernel(const float* __restrict__ pos)
{
    extern __shared__ float sm[];
    float* Qs = sm;               // [128][64] swizzled
    float* Ks = Qs + 8192;        // [64][64]  swizzled
    float* Vs = Ks + 4096;        // [64][64]  row-major
    float* Ps = Vs + 4096;        // [64][128] swizzled over row dim
    float* pq = Ps + 8192;        // [128][2]
    float* pk = pq + 256;         // [64][2]

    const int tid = threadIdx.x;
    const int tx = tid & 15, ty = tid >> 4;
    const int q0 = blockIdx.x * 128;
    const int bh = blockIdx.y;
    const int bi = bh >> 3, head = bh & 7;

    const float* qb = g_q + (size_t)bh * NN * DD;
    const float* kb = g_k + (size_t)bh * NN * DD;
    const float* vb = g_v + (size_t)bh * NN * DD;

#pragma unroll
    for (int s = 0; s < 8; s++) {
        int idx = tid + 256 * s;
        int cf = idx & 15, j = idx >> 4;
        float4 v = *(const float4*)(qb + (size_t)(q0 + j) * 64 + cf * 4);
        int pg = cf ^ ((j >> 2) & 15);
        *(float4*)&Qs[j * 64 + pg * 4] = v;
    }
    if (tid < 128)
        *(float2*)&pq[tid * 2] = *(const float2*)(pos + (size_t)(q0 + tid) * 2);

    u64 o2[8][2];
    float mrow[8], lrow[8];
#pragma unroll
    for (int i = 0; i < 8; i++) {
        mrow[i] = -1e30f; lrow[i] = 0.f;
        o2[i][0] = 0ull; o2[i][1] = 0ull;
    }

    float pqx[8], pqy[8];
    __syncthreads();
#pragma unroll
    for (int i = 0; i < 8; i++) {
        pqx[i] = pq[(ty * 8 + i) * 2 + 0];
        pqy[i] = pq[(ty * 8 + i) * 2 + 1];
    }

    for (int kt = 0; kt < 32; kt++) {
        const int k0 = kt * 64;
        __syncthreads();
#pragma unroll
        for (int s = 0; s < 4; s++) {
            int idx = tid + 256 * s;
            int cf = idx & 15, j = idx >> 4;
            float4 kv4 = *(const float4*)(kb + (size_t)(k0 + j) * 64 + cf * 4);
            int pg = cf ^ ((j >> 2) & 15);
            *(float4*)&Ks[j * 64 + pg * 4] = kv4;
            float4 vv4 = *(const float4*)(vb + (size_t)(k0 + j) * 64 + cf * 4);
            *(float4*)&Vs[j * 64 + cf * 4] = vv4;
        }
        if (tid < 64)
            *(float2*)&pk[tid * 2] = *(const float2*)(pos + (size_t)(k0 + tid) * 2);
        __syncthreads();

        // S = Q K^T — packed along the reduction dim (zero extra movs)
        u64 sacc2[8][4];
#pragma unroll
        for (int i = 0; i < 8; i++)
#pragma unroll
            for (int j = 0; j < 4; j++) sacc2[i][j] = 0ull;

#pragma unroll
        for (int g = 0; g < 16; g++) {
            ulonglong2 kv2[4];
#pragma unroll
            for (int jj = 0; jj < 4; jj++) {
                int r = tx * 4 + jj;
                kv2[jj] = *(const ulonglong2*)&Ks[r * 64 + ((g ^ tx) & 15) * 4];
            }
#pragma unroll
            for (int i = 0; i < 8; i++) {
                int row = ty * 8 + i;
                ulonglong2 qv2 =
                    *(const ulonglong2*)&Qs[row * 64 + ((g ^ ((row >> 2) & 15)) & 15) * 4];
#pragma unroll
                for (int jj = 0; jj < 4; jj++) {
                    sacc2[i][jj] = ffma2(qv2.x, kv2[jj].x, sacc2[i][jj]);
                    sacc2[i][jj] = ffma2(qv2.y, kv2[jj].y, sacc2[i][jj]);
                }
            }
        }

        float pkx[4], pky[4];
#pragma unroll
        for (int jj = 0; jj < 4; jj++) {
            pkx[jj] = pk[(tx * 4 + jj) * 2 + 0];
            pky[jj] = pk[(tx * 4 + jj) * 2 + 1];
        }

        float pexp[8][4];
#pragma unroll
        for (int i = 0; i < 8; i++) {
            float sv[4];
            float rmax = -1e30f;
#pragma unroll
            for (int jj = 0; jj < 4; jj++) {
                float2 t = unpack2(sacc2[i][jj]);
                float dx = fabsf(pqx[i] - pkx[jj]); dx += 0.5f; dx -= floorf(dx); dx -= 0.5f;
                float dy = fabsf(pqy[i] - pky[jj]); dy += 0.5f; dy -= floorf(dy); dy -= 0.5f;
                float s = (t.x + t.y) * 0.125f - (dx * dx + dy * dy);
                sv[jj] = s;
                rmax = fmaxf(rmax, s);
            }
#pragma unroll
            for (int off = 8; off >= 1; off >>= 1)
                rmax = fmaxf(rmax, __shfl_xor_sync(0xffffffffu, rmax, off));
            float mnew = fmaxf(mrow[i], rmax);
            float corr = __expf(mrow[i] - mnew);
            float rsum = 0.f;
#pragma unroll
            for (int jj = 0; jj < 4; jj++) {
                float p = __expf(sv[jj] - mnew);
                pexp[i][jj] = p;
                rsum += p;
            }
#pragma unroll
            for (int off = 8; off >= 1; off >>= 1)
                rsum += __shfl_xor_sync(0xffffffffu, rsum, off);
            lrow[i] = lrow[i] * corr + rsum;
            mrow[i] = mnew;
            u64 corrd = pack2(corr, corr);
            o2[i][0] = fmul2(o2[i][0], corrd);
            o2[i][1] = fmul2(o2[i][1], corrd);
        }

        // store P transposed (swizzled): Ps[kk][row]
#pragma unroll
        for (int jj = 0; jj < 4; jj++) {
            int kk = tx * 4 + jj;
#pragma unroll
            for (int h = 0; h < 2; h++) {
                int pg = (2 * ty + h) ^ tx;
                float4 pv = make_float4(pexp[4 * h + 0][jj], pexp[4 * h + 1][jj],
                                        pexp[4 * h + 2][jj], pexp[4 * h + 3][jj]);
                *(float4*)&Ps[kk * 128 + pg * 4] = pv;
            }
        }
        __syncthreads();

        // O += P @ V — packed along output columns
#pragma unroll
        for (int kk = 0; kk < 64; kk++) {
            ulonglong2 vv2 = *(const ulonglong2*)&Vs[kk * 64 + tx * 4];
            int swk = (kk >> 2) & 15;
            float4 p0 = *(const float4*)&Ps[kk * 128 + ((2 * ty) ^ swk) * 4];
            float4 p1 = *(const float4*)&Ps[kk * 128 + ((2 * ty + 1) ^ swk) * 4];
            float pr[8] = {p0.x, p0.y, p0.z, p0.w, p1.x, p1.y, p1.z, p1.w};
#pragma unroll
            for (int i = 0; i < 8; i++) {
                u64 prd = pack2(pr[i], pr[i]);
                o2[i][0] = ffma2(prd, vv2.x, o2[i][0]);
                o2[i][1] = ffma2(prd, vv2.y, o2[i][1]);
            }
        }
    }

#pragma unroll
    for (int i = 0; i < 8; i++) {
        float inv = 1.0f / lrow[i];
        int row = q0 + ty * 8 + i;
        float2 a = unpack2(o2[i][0]);
        float2 b = unpack2(o2[i][1]);
        float4 r = make_float4(a.x * inv, a.y * inv, b.x * inv, b.y * inv);
        *(float4*)&g_att[((size_t)bi * NN + row) * DIM + head * 64 + tx * 4] = r;
    }
}

// ---------------------------------------------------------------------------
// Kernel 4: output GEMM.  out[4096,512] = g_att @ W_out[512,512] + b_out
// ---------------------------------------------------------------------------
__global__ __launch_bounds__(256, 1) void out_gemm_kernel(
    const float* __restrict__ W, const float* __restrict__ bout, float* __restrict__ out)
{
    __shared__ float AsT[16][132];
    __shared__ float Bs[16][132];

    const int tid = threadIdx.x;
    const int tx = tid & 15, ty = tid >> 4;
    const int row0 = blockIdx.y * 128;
    const int col0 = blockIdx.x * 128;

    u64 acc2[8][4];
#pragma unroll
    for (int i = 0; i < 8; i++)
#pragma unroll
        for (int j = 0; j < 4; j++) acc2[i][j] = 0ull;

    for (int k0 = 0; k0 < 512; k0 += 16) {
#pragma unroll
        for (int s = 0; s < 2; s++) {
            int idx = tid + s * 256;
            int r = idx >> 2, c4 = idx & 3;
            float4 va = *(const float4*)(g_att + (size_t)(row0 + r) * 512 + k0 + c4 * 4);
            AsT[c4 * 4 + 0][r] = va.x;
            AsT[c4 * 4 + 1][r] = va.y;
            AsT[c4 * 4 + 2][r] = va.z;
            AsT[c4 * 4 + 3][r] = va.w;
            int kr = idx >> 5, cc = idx & 31;
            *(float4*)&Bs[kr][cc * 4] =
                *(const float4*)(W + (size_t)(k0 + kr) * 512 + col0 + cc * 4);
        }
        __syncthreads();
#pragma unroll
        for (int kk = 0; kk < 16; kk++) {
            float4 a0 = *(float4*)&AsT[kk][ty * 8];
            float4 a1 = *(float4*)&AsT[kk][ty * 8 + 4];
            ulonglong2 b0 = *(ulonglong2*)&Bs[kk][tx * 4];
            ulonglong2 b1 = *(ulonglong2*)&Bs[kk][64 + tx * 4];
            float a[8] = {a0.x, a0.y, a0.z, a0.w, a1.x, a1.y, a1.z, a1.w};
#pragma unroll
            for (int i = 0; i < 8; i++) {
                u64 ad = pack2(a[i], a[i]);
                acc2[i][0] = ffma2(ad, b0.x, acc2[i][0]);
                acc2[i][1] = ffma2(ad, b0.y, acc2[i][1]);
                acc2[i][2] = ffma2(ad, b1.x, acc2[i][2]);
                acc2[i][3] = ffma2(ad, b1.y, acc2[i][3]);
            }
        }
        __syncthreads();
    }

#pragma unroll
    for (int i = 0; i < 8; i++) {
        int m = row0 + ty * 8 + i;
#pragma unroll
        for (int half = 0; half < 2; half++) {
            int c = col0 + half * 64 + tx * 4;
            float4 bv = *(const float4*)(bout + c);
            float2 p0 = unpack2(acc2[i][half * 2 + 0]);
            float2 p1 = unpack2(acc2[i][half * 2 + 1]);
            float4 r;
            r.x = p0.x + bv.x;
            r.y = p0.y + bv.y;
            r.z = p1.x + bv.z;
            r.w = p1.y + bv.w;
            *(float4*)&out[(size_t)m * 512 + c] = r;
        }
    }
}

// ---------------------------------------------------------------------------
extern "C" void kernel_launch(void* const* d_in, const int* in_sizes, int n_in,
                              void* d_out, int out_size)
{
    const float* x    = (const float*)d_in[0];
    const float* pos  = (const float*)d_in[1];
    const float* W_in = (const float*)d_in[2];
    const float* b_in = (const float*)d_in[3];
    const float* qn_w = (const float*)d_in[4];
    const float* qn_b = (const float*)d_in[5];
    const float* kn_w = (const float*)d_in[6];
    const float* kn_b = (const float*)d_in[7];
    const float* W_out= (const float*)d_in[8];
    const float* b_out= (const float*)d_in[9];
    float* out = (float*)d_out;

    qkv_gemm_kernel<<<dim3(12, 32), 256>>>(x, W_in, b_in);
    ln_qk_kernel<<<(2 * BHD * NN) / 8, 256>>>(qn_w, qn_b, kn_w, kn_b);

    cudaFuncSetAttribute(attn_kernel, cudaFuncAttributeMaxDynamicSharedMemorySize,
                         ATTN_SMEM_BYTES);
    attn_kernel<<<dim3(16, 16), 256, ATTN_SMEM_BYTES>>>(pos);

    out_gemm_kernel<<<dim3(4, 32), 256>>>(W_out, b_out, out);
}

// round 3
// speedup vs baseline: 1.1701x; 1.0108x over previous
#include <cuda_runtime.h>
#include <cuda_bf16.h>
#include <math.h>

#define BB   2
#define NN   2048
#define DIM  512
#define HH   8
#define DD   64
#define BN   (BB*NN)    // 4096
#define BHD  (BB*HH)    // 16

// Scratch (allocation-free)
__device__ float g_q[BHD*NN*DD];
__device__ float g_k[BHD*NN*DD];
__device__ float g_v[BHD*NN*DD];
__device__ float g_att[BN*DIM];

// ---------------------------------------------------------------------------
// packed f32x2 helpers (SASS FFMA2 path — only reachable via PTX)
// ---------------------------------------------------------------------------
typedef unsigned long long u64;

__device__ __forceinline__ u64 ffma2(u64 a, u64 b, u64 c) {
    u64 d;
    asm("fma.rn.f32x2 %0, %1, %2, %3;" : "=l"(d) : "l"(a), "l"(b), "l"(c));
    return d;
}
__device__ __forceinline__ u64 pack2(float x, float y) {
    u64 r;
    asm("mov.b64 %0, {%1, %2};" : "=l"(r) : "f"(x), "f"(y));
    return r;
}
__device__ __forceinline__ float2 unpack2(u64 v) {
    float2 r;
    asm("mov.b64 {%0, %1}, %2;" : "=f"(r.x), "=f"(r.y) : "l"(v));
    return r;
}

// ---------------------------------------------------------------------------
// Kernel 1: QKV GEMM.  C[4096,1536] = x[4096,512] @ W_in[512,1536] + b_in
// 128x128 tile, 256 threads, 8x8 micro-tile, FFMA2. occ 2.
// ---------------------------------------------------------------------------
__global__ __launch_bounds__(256, 2) void qkv_gemm_kernel(
    const float* __restrict__ x, const float* __restrict__ W,
    const float* __restrict__ bin)
{
    __shared__ float AsT[16][132];
    __shared__ float Bs[16][132];

    const int tid = threadIdx.x;
    const int tx = tid & 15, ty = tid >> 4;
    const int row0 = blockIdx.y * 128;
    const int col0 = blockIdx.x * 128;

    u64 acc2[8][4];
#pragma unroll
    for (int i = 0; i < 8; i++)
#pragma unroll
        for (int j = 0; j < 4; j++) acc2[i][j] = 0ull;

    for (int k0 = 0; k0 < 512; k0 += 16) {
#pragma unroll
        for (int s = 0; s < 2; s++) {
            int idx = tid + s * 256;
            int r = idx >> 2, c4 = idx & 3;
            float4 va = *(const float4*)(x + (size_t)(row0 + r) * 512 + k0 + c4 * 4);
            AsT[c4 * 4 + 0][r] = va.x;
            AsT[c4 * 4 + 1][r] = va.y;
            AsT[c4 * 4 + 2][r] = va.z;
            AsT[c4 * 4 + 3][r] = va.w;
            int kr = idx >> 5, cc = idx & 31;
            *(float4*)&Bs[kr][cc * 4] =
                *(const float4*)(W + (size_t)(k0 + kr) * 1536 + col0 + cc * 4);
        }
        __syncthreads();
#pragma unroll
        for (int kk = 0; kk < 16; kk++) {
            float4 a0 = *(float4*)&AsT[kk][ty * 8];
            float4 a1 = *(float4*)&AsT[kk][ty * 8 + 4];
            ulonglong2 b0 = *(ulonglong2*)&Bs[kk][tx * 4];
            ulonglong2 b1 = *(ulonglong2*)&Bs[kk][64 + tx * 4];
            float a[8] = {a0.x, a0.y, a0.z, a0.w, a1.x, a1.y, a1.z, a1.w};
#pragma unroll
            for (int i = 0; i < 8; i++) {
                u64 ad = pack2(a[i], a[i]);
                acc2[i][0] = ffma2(ad, b0.x, acc2[i][0]);
                acc2[i][1] = ffma2(ad, b0.y, acc2[i][1]);
                acc2[i][2] = ffma2(ad, b1.x, acc2[i][2]);
                acc2[i][3] = ffma2(ad, b1.y, acc2[i][3]);
            }
        }
        __syncthreads();
    }

#pragma unroll
    for (int i = 0; i < 8; i++) {
        int m  = row0 + ty * 8 + i;
        int bi = m >> 11;
        int ni = m & 2047;
#pragma unroll
        for (int half = 0; half < 2; half++) {
            int c = col0 + half * 64 + tx * 4;
            float4 bv = *(const float4*)(bin + c);
            float2 p0 = unpack2(acc2[i][half * 2 + 0]);
            float2 p1 = unpack2(acc2[i][half * 2 + 1]);
            float4 r;
            r.x = p0.x + bv.x;
            r.y = p0.y + bv.y;
            r.z = p1.x + bv.z;
            r.w = p1.y + bv.w;
            int three = c >> 9;
            int head  = (c >> 6) & 7;
            float* dst = (three == 0) ? g_q : (three == 1) ? g_k : g_v;
            size_t off = (((size_t)bi * HH + head) * NN + ni) * DD + (c & 63);
            *(float4*)&dst[off] = r;
        }
    }
}

// ---------------------------------------------------------------------------
// Kernel 2: per-head LayerNorm on q and k rows (d=64). One warp per row.
// ---------------------------------------------------------------------------
__global__ void ln_qk_kernel(const float* __restrict__ qn_w, const float* __restrict__ qn_b,
                             const float* __restrict__ kn_w, const float* __restrict__ kn_b)
{
    const int ROWS = BHD * NN;
    int gid = blockIdx.x * 8 + (threadIdx.x >> 5);
    int lane = threadIdx.x & 31;
    if (gid >= 2 * ROWS) return;
    bool isq = gid < ROWS;
    int r = isq ? gid : gid - ROWS;
    float* buf = isq ? g_q : g_k;
    const float* w = isq ? qn_w : kn_w;
    const float* bb = isq ? qn_b : kn_b;

    float x0 = buf[(size_t)r * 64 + lane];
    float x1 = buf[(size_t)r * 64 + 32 + lane];
    float s = x0 + x1;
#pragma unroll
    for (int off = 16; off >= 1; off >>= 1) s += __shfl_xor_sync(0xffffffffu, s, off);
    float mu = s * (1.0f / 64.0f);
    float d0 = x0 - mu, d1 = x1 - mu;
    float v = d0 * d0 + d1 * d1;
#pragma unroll
    for (int off = 16; off >= 1; off >>= 1) v += __shfl_xor_sync(0xffffffffu, v, off);
    float inv = rsqrtf(v * (1.0f / 64.0f) + 1e-5f);
    buf[(size_t)r * 64 + lane]      = d0 * inv * w[lane] + bb[lane];
    buf[(size_t)r * 64 + 32 + lane] = d1 * inv * w[lane + 32] + bb[lane + 32];
}

// ---------------------------------------------------------------------------
// Kernel 3: flash attention with positional bias.
// Fixed-max softmax: after LN, ||q||=||k||=8 exactly => s = q.k/8 + bias <= 8.
// exp(s - 8) is exact softmax with constant max -> no running max, no corr,
// no in-loop shuffles. Per-thread partial row sums, one reduction at the end.
// ---------------------------------------------------------------------------
#define ATTN_SMEM_FLOATS (8192 + 4096 + 4096 + 8192 + 256 + 128)
#define ATTN_SMEM_BYTES  (ATTN_SMEM_FLOATS * 4)

__global__ __launch_bounds__(256, 1) void attn_kernel(const float* __restrict__ pos)
{
    extern __shared__ float sm[];
    float* Qs = sm;               // [128][64] swizzled
    float* Ks = Qs + 8192;        // [64][64]  swizzled
    float* Vs = Ks + 4096;        // [64][64]  row-major
    float* Ps = Vs + 4096;        // [64][128] swizzled over row dim
    float* pq = Ps + 8192;        // [128][2]
    float* pk = pq + 256;         // [64][2]

    const int tid = threadIdx.x;
    const int tx = tid & 15, ty = tid >> 4;
    const int q0 = blockIdx.x * 128;
    const int bh = blockIdx.y;
    const int bi = bh >> 3, head = bh & 7;

    const float* qb = g_q + (size_t)bh * NN * DD;
    const float* kb = g_k + (size_t)bh * NN * DD;
    const float* vb = g_v + (size_t)bh * NN * DD;

#pragma unroll
    for (int s = 0; s < 8; s++) {
        int idx = tid + 256 * s;
        int cf = idx & 15, j = idx >> 4;
        float4 v = *(const float4*)(qb + (size_t)(q0 + j) * 64 + cf * 4);
        int pg = cf ^ ((j >> 2) & 15);
        *(float4*)&Qs[j * 64 + pg * 4] = v;
    }
    if (tid < 128)
        *(float2*)&pq[tid * 2] = *(const float2*)(pos + (size_t)(q0 + tid) * 2);

    u64 o2[8][2];
    float lsum[8];
#pragma unroll
    for (int i = 0; i < 8; i++) {
        lsum[i] = 0.f;
        o2[i][0] = 0ull; o2[i][1] = 0ull;
    }

    float pqx[8], pqy[8];
    __syncthreads();
#pragma unroll
    for (int i = 0; i < 8; i++) {
        pqx[i] = pq[(ty * 8 + i) * 2 + 0];
        pqy[i] = pq[(ty * 8 + i) * 2 + 1];
    }

    for (int kt = 0; kt < 32; kt++) {
        const int k0 = kt * 64;
        __syncthreads();
#pragma unroll
        for (int s = 0; s < 4; s++) {
            int idx = tid + 256 * s;
            int cf = idx & 15, j = idx >> 4;
            float4 kv4 = *(const float4*)(kb + (size_t)(k0 + j) * 64 + cf * 4);
            int pg = cf ^ ((j >> 2) & 15);
            *(float4*)&Ks[j * 64 + pg * 4] = kv4;
            float4 vv4 = *(const float4*)(vb + (size_t)(k0 + j) * 64 + cf * 4);
            *(float4*)&Vs[j * 64 + cf * 4] = vv4;
        }
        if (tid < 64)
            *(float2*)&pk[tid * 2] = *(const float2*)(pos + (size_t)(k0 + tid) * 2);
        __syncthreads();

        // S = Q K^T — packed along the reduction dim
        u64 sacc2[8][4];
#pragma unroll
        for (int i = 0; i < 8; i++)
#pragma unroll
            for (int j = 0; j < 4; j++) sacc2[i][j] = 0ull;

#pragma unroll
        for (int g = 0; g < 16; g++) {
            ulonglong2 kv2[4];
#pragma unroll
            for (int jj = 0; jj < 4; jj++) {
                int r = tx * 4 + jj;
                kv2[jj] = *(const ulonglong2*)&Ks[r * 64 + ((g ^ tx) & 15) * 4];
            }
#pragma unroll
            for (int i = 0; i < 8; i++) {
                int row = ty * 8 + i;
                ulonglong2 qv2 =
                    *(const ulonglong2*)&Qs[row * 64 + ((g ^ ((row >> 2) & 15)) & 15) * 4];
#pragma unroll
                for (int jj = 0; jj < 4; jj++) {
                    sacc2[i][jj] = ffma2(qv2.x, kv2[jj].x, sacc2[i][jj]);
                    sacc2[i][jj] = ffma2(qv2.y, kv2[jj].y, sacc2[i][jj]);
                }
            }
        }

        float pkx[4], pky[4];
#pragma unroll
        for (int jj = 0; jj < 4; jj++) {
            pkx[jj] = pk[(tx * 4 + jj) * 2 + 0];
            pky[jj] = pk[(tx * 4 + jj) * 2 + 1];
        }

        // softmax numerator with constant max 8:
        // p = exp2( (s/8 - edist - 8) * log2e )
        float pexp[8][4];
#pragma unroll
        for (int i = 0; i < 8; i++) {
#pragma unroll
            for (int jj = 0; jj < 4; jj++) {
                float2 t = unpack2(sacc2[i][jj]);
                float dx = fabsf(pqx[i] - pkx[jj]); dx = fminf(dx, 1.0f - dx);
                float dy = fabsf(pqy[i] - pky[jj]); dy = fminf(dy, 1.0f - dy);
                float s = (t.x + t.y) * 0.125f - (dx * dx + dy * dy);
                float p = exp2f(fmaf(s, 1.44269504f, -11.54156036f));
                pexp[i][jj] = p;
                lsum[i] += p;
            }
        }

        // store P transposed (swizzled): Ps[kk][row]
#pragma unroll
        for (int jj = 0; jj < 4; jj++) {
            int kk = tx * 4 + jj;
#pragma unroll
            for (int h = 0; h < 2; h++) {
                int pg = (2 * ty + h) ^ tx;
                float4 pv = make_float4(pexp[4 * h + 0][jj], pexp[4 * h + 1][jj],
                                        pexp[4 * h + 2][jj], pexp[4 * h + 3][jj]);
                *(float4*)&Ps[kk * 128 + pg * 4] = pv;
            }
        }
        __syncthreads();

        // O += P @ V — packed along output columns, no rescale needed
#pragma unroll
        for (int kk = 0; kk < 64; kk++) {
            ulonglong2 vv2 = *(const ulonglong2*)&Vs[kk * 64 + tx * 4];
            int swk = (kk >> 2) & 15;
            float4 p0 = *(const float4*)&Ps[kk * 128 + ((2 * ty) ^ swk) * 4];
            float4 p1 = *(const float4*)&Ps[kk * 128 + ((2 * ty + 1) ^ swk) * 4];
            float pr[8] = {p0.x, p0.y, p0.z, p0.w, p1.x, p1.y, p1.z, p1.w};
#pragma unroll
            for (int i = 0; i < 8; i++) {
                u64 prd = pack2(pr[i], pr[i]);
                o2[i][0] = ffma2(prd, vv2.x, o2[i][0]);
                o2[i][1] = ffma2(prd, vv2.y, o2[i][1]);
            }
        }
    }

    // final: reduce row sums across the 16 tx lanes (within warp), normalize
#pragma unroll
    for (int i = 0; i < 8; i++) {
        float l = lsum[i];
#pragma unroll
        for (int off = 8; off >= 1; off >>= 1)
            l += __shfl_xor_sync(0xffffffffu, l, off);
        float inv = 1.0f / l;
        int row = q0 + ty * 8 + i;
        float2 a = unpack2(o2[i][0]);
        float2 b = unpack2(o2[i][1]);
        float4 r = make_float4(a.x * inv, a.y * inv, b.x * inv, b.y * inv);
        *(float4*)&g_att[((size_t)bi * NN + row) * DIM + head * 64 + tx * 4] = r;
    }
}

// ---------------------------------------------------------------------------
// Kernel 4: output GEMM.  out[4096,512] = g_att @ W_out[512,512] + b_out
// 64x64 tiles (grid 512 for full-chip occupancy), 4x4 micro, FFMA2.
// ---------------------------------------------------------------------------
__global__ __launch_bounds__(256, 3) void out_gemm_kernel(
    const float* __restrict__ W, const float* __restrict__ bout, float* __restrict__ out)
{
    __shared__ float AsT[16][68];
    __shared__ float Bs[16][68];

    const int tid = threadIdx.x;
    const int tx = tid & 15, ty = tid >> 4;
    const int row0 = blockIdx.y * 64;
    const int col0 = blockIdx.x * 64;

    u64 acc2[4][2];
#pragma unroll
    for (int i = 0; i < 4; i++) { acc2[i][0] = 0ull; acc2[i][1] = 0ull; }

    for (int k0 = 0; k0 < 512; k0 += 16) {
        {
            int r = tid >> 2, c4 = tid & 3;
            float4 va = *(const float4*)(g_att + (size_t)(row0 + r) * 512 + k0 + c4 * 4);
            AsT[c4 * 4 + 0][r] = va.x;
            AsT[c4 * 4 + 1][r] = va.y;
            AsT[c4 * 4 + 2][r] = va.z;
            AsT[c4 * 4 + 3][r] = va.w;
            int kr = tid >> 4, cc = tid & 15;
            *(float4*)&Bs[kr][cc * 4] =
                *(const float4*)(W + (size_t)(k0 + kr) * 512 + col0 + cc * 4);
        }
        __syncthreads();
#pragma unroll
        for (int kk = 0; kk < 16; kk++) {
            float4 a4 = *(float4*)&AsT[kk][ty * 4];
            ulonglong2 b2 = *(ulonglong2*)&Bs[kk][tx * 4];
            float a[4] = {a4.x, a4.y, a4.z, a4.w};
#pragma unroll
            for (int i = 0; i < 4; i++) {
                u64 ad = pack2(a[i], a[i]);
                acc2[i][0] = ffma2(ad, b2.x, acc2[i][0]);
                acc2[i][1] = ffma2(ad, b2.y, acc2[i][1]);
            }
        }
        __syncthreads();
    }

    int c = col0 + tx * 4;
    float4 bv = *(const float4*)(bout + c);
#pragma unroll
    for (int i = 0; i < 4; i++) {
        int m = row0 + ty * 4 + i;
        float2 p0 = unpack2(acc2[i][0]);
        float2 p1 = unpack2(acc2[i][1]);
        float4 r;
        r.x = p0.x + bv.x;
        r.y = p0.y + bv.y;
        r.z = p1.x + bv.z;
        r.w = p1.y + bv.w;
        *(float4*)&out[(size_t)m * 512 + c] = r;
    }
}

// ---------------------------------------------------------------------------
extern "C" void kernel_launch(void* const* d_in, const int* in_sizes, int n_in,
                              void* d_out, int out_size)
{
    const float* x    = (const float*)d_in[0];
    const float* pos  = (const float*)d_in[1];
    const float* W_in = (const float*)d_in[2];
    const float* b_in = (const float*)d_in[3];
    const float* qn_w = (const float*)d_in[4];
    const float* qn_b = (const float*)d_in[5];
    const float* kn_w = (const float*)d_in[6];
    const float* kn_b = (const float*)d_in[7];
    const float* W_out= (const float*)d_in[8];
    const float* b_out= (const float*)d_in[9];
    float* out = (float*)d_out;

    qkv_gemm_kernel<<<dim3(12, 32), 256>>>(x, W_in, b_in);
    ln_qk_kernel<<<(2 * BHD * NN) / 8, 256>>>(qn_w, qn_b, kn_w, kn_b);

    cudaFuncSetAttribute(attn_kernel, cudaFuncAttributeMaxDynamicSharedMemorySize,
                         ATTN_SMEM_BYTES);
    attn_kernel<<<dim3(16, 16), 256, ATTN_SMEM_BYTES>>>(pos);

    out_gemm_kernel<<<dim3(8, 64), 256>>>(W_out, b_out, out);
}

// round 5
// speedup vs baseline: 1.8160x; 1.5520x over previous
#include <cuda_runtime.h>
#include <cuda_bf16.h>
#include <math.h>
#include <stdint.h>

#define BB   2
#define NN   2048
#define DIM  512
#define HH   8
#define DD   64
#define BN   (BB*NN)    // 4096
#define BHD  (BB*HH)    // 16

// Scratch (allocation-free)
__device__ float g_q[BHD*NN*DD];
__device__ float g_k[BHD*NN*DD];
__device__ float g_v[BHD*NN*DD];
__device__ float g_att[BN*DIM];

typedef unsigned long long u64;
typedef unsigned int u32;

// ---------------------------------------------------------------------------
// packed f32x2 helpers (FFMA2 for scalar GEMMs)
// ---------------------------------------------------------------------------
__device__ __forceinline__ u64 ffma2(u64 a, u64 b, u64 c) {
    u64 d;
    asm("fma.rn.f32x2 %0, %1, %2, %3;" : "=l"(d) : "l"(a), "l"(b), "l"(c));
    return d;
}
__device__ __forceinline__ u64 pack2(float x, float y) {
    u64 r;
    asm("mov.b64 %0, {%1, %2};" : "=l"(r) : "f"(x), "f"(y));
    return r;
}
__device__ __forceinline__ float2 unpack2(u64 v) {
    float2 r;
    asm("mov.b64 {%0, %1}, %2;" : "=f"(r.x), "=f"(r.y) : "l"(v));
    return r;
}

// ---------------------------------------------------------------------------
// mma.sync bf16 helpers
// ---------------------------------------------------------------------------
__device__ __forceinline__ void mma16816(float* c,
    u32 a0, u32 a1, u32 a2, u32 a3, u32 b0, u32 b1)
{
    asm volatile(
        "mma.sync.aligned.m16n8k16.row.col.f32.bf16.bf16.f32 "
        "{%0,%1,%2,%3}, {%4,%5,%6,%7}, {%8,%9}, {%0,%1,%2,%3};"
        : "+f"(c[0]), "+f"(c[1]), "+f"(c[2]), "+f"(c[3])
        : "r"(a0), "r"(a1), "r"(a2), "r"(a3), "r"(b0), "r"(b1));
}

__device__ __forceinline__ u32 pack_bf(__nv_bfloat16 a, __nv_bfloat16 b) {
    u32 lo = (u32)__bfloat16_as_ushort(a);
    u32 hi = (u32)__bfloat16_as_ushort(b);
    return lo | (hi << 16);
}
__device__ __forceinline__ u32 pack_hi2(float x, float y) {
    return pack_bf(__float2bfloat16(x), __float2bfloat16(y));
}
__device__ __forceinline__ u32 pack_lo2(float x, float y) {
    __nv_bfloat16 hx = __float2bfloat16(x), hy = __float2bfloat16(y);
    return pack_bf(__float2bfloat16(x - __bfloat162float(hx)),
                   __float2bfloat16(y - __bfloat162float(hy)));
}

// ---------------------------------------------------------------------------
// Kernel 1: QKV GEMM (scalar FFMA2, known good).
// ---------------------------------------------------------------------------
__global__ __launch_bounds__(256, 2) void qkv_gemm_kernel(
    const float* __restrict__ x, const float* __restrict__ W,
    const float* __restrict__ bin)
{
    __shared__ float AsT[16][132];
    __shared__ float Bs[16][132];

    const int tid = threadIdx.x;
    const int tx = tid & 15, ty = tid >> 4;
    const int row0 = blockIdx.y * 128;
    const int col0 = blockIdx.x * 128;

    u64 acc2[8][4];
#pragma unroll
    for (int i = 0; i < 8; i++)
#pragma unroll
        for (int j = 0; j < 4; j++) acc2[i][j] = 0ull;

    for (int k0 = 0; k0 < 512; k0 += 16) {
#pragma unroll
        for (int s = 0; s < 2; s++) {
            int idx = tid + s * 256;
            int r = idx >> 2, c4 = idx & 3;
            float4 va = *(const float4*)(x + (size_t)(row0 + r) * 512 + k0 + c4 * 4);
            AsT[c4 * 4 + 0][r] = va.x;
            AsT[c4 * 4 + 1][r] = va.y;
            AsT[c4 * 4 + 2][r] = va.z;
            AsT[c4 * 4 + 3][r] = va.w;
            int kr = idx >> 5, cc = idx & 31;
            *(float4*)&Bs[kr][cc * 4] =
                *(const float4*)(W + (size_t)(k0 + kr) * 1536 + col0 + cc * 4);
        }
        __syncthreads();
#pragma unroll
        for (int kk = 0; kk < 16; kk++) {
            float4 a0 = *(float4*)&AsT[kk][ty * 8];
            float4 a1 = *(float4*)&AsT[kk][ty * 8 + 4];
            ulonglong2 b0 = *(ulonglong2*)&Bs[kk][tx * 4];
            ulonglong2 b1 = *(ulonglong2*)&Bs[kk][64 + tx * 4];
            float a[8] = {a0.x, a0.y, a0.z, a0.w, a1.x, a1.y, a1.z, a1.w};
#pragma unroll
            for (int i = 0; i < 8; i++) {
                u64 ad = pack2(a[i], a[i]);
                acc2[i][0] = ffma2(ad, b0.x, acc2[i][0]);
                acc2[i][1] = ffma2(ad, b0.y, acc2[i][1]);
                acc2[i][2] = ffma2(ad, b1.x, acc2[i][2]);
                acc2[i][3] = ffma2(ad, b1.y, acc2[i][3]);
            }
        }
        __syncthreads();
    }

#pragma unroll
    for (int i = 0; i < 8; i++) {
        int m  = row0 + ty * 8 + i;
        int bi = m >> 11;
        int ni = m & 2047;
#pragma unroll
        for (int half = 0; half < 2; half++) {
            int c = col0 + half * 64 + tx * 4;
            float4 bv = *(const float4*)(bin + c);
            float2 p0 = unpack2(acc2[i][half * 2 + 0]);
            float2 p1 = unpack2(acc2[i][half * 2 + 1]);
            float4 r;
            r.x = p0.x + bv.x;
            r.y = p0.y + bv.y;
            r.z = p1.x + bv.z;
            r.w = p1.y + bv.w;
            int three = c >> 9;
            int head  = (c >> 6) & 7;
            float* dst = (three == 0) ? g_q : (three == 1) ? g_k : g_v;
            size_t off = (((size_t)bi * HH + head) * NN + ni) * DD + (c & 63);
            *(float4*)&dst[off] = r;
        }
    }
}

// ---------------------------------------------------------------------------
// Kernel 2: per-head LayerNorm on q and k rows (d=64). One warp per row.
// ---------------------------------------------------------------------------
__global__ void ln_qk_kernel(const float* __restrict__ qn_w, const float* __restrict__ qn_b,
                             const float* __restrict__ kn_w, const float* __restrict__ kn_b)
{
    const int ROWS = BHD * NN;
    int gid = blockIdx.x * 8 + (threadIdx.x >> 5);
    int lane = threadIdx.x & 31;
    if (gid >= 2 * ROWS) return;
    bool isq = gid < ROWS;
    int r = isq ? gid : gid - ROWS;
    float* buf = isq ? g_q : g_k;
    const float* w = isq ? qn_w : kn_w;
    const float* bb = isq ? qn_b : kn_b;

    float x0 = buf[(size_t)r * 64 + lane];
    float x1 = buf[(size_t)r * 64 + 32 + lane];
    float s = x0 + x1;
#pragma unroll
    for (int off = 16; off >= 1; off >>= 1) s += __shfl_xor_sync(0xffffffffu, s, off);
    float mu = s * (1.0f / 64.0f);
    float d0 = x0 - mu, d1 = x1 - mu;
    float v = d0 * d0 + d1 * d1;
#pragma unroll
    for (int off = 16; off >= 1; off >>= 1) v += __shfl_xor_sync(0xffffffffu, v, off);
    float inv = rsqrtf(v * (1.0f / 64.0f) + 1e-5f);
    buf[(size_t)r * 64 + lane]      = d0 * inv * w[lane] + bb[lane];
    buf[(size_t)r * 64 + 32 + lane] = d1 * inv * w[lane + 32] + bb[lane + 32];
}

// ---------------------------------------------------------------------------
// Kernel 3: flash attention via mma.sync bf16 hi/lo (3-term), fixed-max softmax.
// 128 q-rows per CTA (8 warps x 16 rows), 64-key tiles.
// Smem rows padded to 72 bf16 (36 banks) -> conflict-free bf16x2 frag loads.
// ---------------------------------------------------------------------------
#define QS 72
#define SM_QHI   0
#define SM_QLO   (SM_QHI  + 128*QS*2)
#define SM_KHI   (SM_QLO  + 128*QS*2)
#define SM_KLO   (SM_KHI  + 64*QS*2)
#define SM_VTHI  (SM_KLO  + 64*QS*2)
#define SM_VTLO  (SM_VTHI + 64*QS*2)
#define SM_PK    (SM_VTLO + 64*QS*2)
#define ATTN_SMEM_BYTES (SM_PK + 64*2*4)

__global__ __launch_bounds__(256, 2) void attn_kernel(const float* __restrict__ pos)
{
    extern __shared__ char smc[];
    __nv_bfloat16* Qhi  = (__nv_bfloat16*)(smc + SM_QHI);
    __nv_bfloat16* Qlo  = (__nv_bfloat16*)(smc + SM_QLO);
    __nv_bfloat16* Khi  = (__nv_bfloat16*)(smc + SM_KHI);
    __nv_bfloat16* Klo  = (__nv_bfloat16*)(smc + SM_KLO);
    __nv_bfloat16* Vthi = (__nv_bfloat16*)(smc + SM_VTHI);
    __nv_bfloat16* Vtlo = (__nv_bfloat16*)(smc + SM_VTLO);
    float* pks = (float*)(smc + SM_PK);

    const int tid = threadIdx.x;
    const int w = tid >> 5, lane = tid & 31;
    const int qr = lane >> 2, qc = lane & 3;
    const int q0 = blockIdx.x * 128;
    const int bh = blockIdx.y;
    const int bi = bh >> 3, head = bh & 7;

    const float* qb = g_q + (size_t)bh * NN * DD;
    const float* kb = g_k + (size_t)bh * NN * DD;
    const float* vb = g_v + (size_t)bh * NN * DD;

    // Load Q -> Qhi/Qlo (128x64, padded rows)
#pragma unroll
    for (int s = 0; s < 8; s++) {
        int idx = tid + 256 * s;
        int r = idx >> 4, c4 = (idx & 15) * 4;
        float4 v = *(const float4*)(qb + (size_t)(q0 + r) * 64 + c4);
        *(u32*)&Qhi[r * QS + c4]     = pack_hi2(v.x, v.y);
        *(u32*)&Qhi[r * QS + c4 + 2] = pack_hi2(v.z, v.w);
        *(u32*)&Qlo[r * QS + c4]     = pack_lo2(v.x, v.y);
        *(u32*)&Qlo[r * QS + c4 + 2] = pack_lo2(v.z, v.w);
    }

    // query positions for this thread's two rows (fixed all kernel)
    const int lrow0 = w * 16 + qr;
    float pqx0 = pos[(q0 + lrow0) * 2 + 0], pqy0 = pos[(q0 + lrow0) * 2 + 1];
    float pqx1 = pos[(q0 + lrow0 + 8) * 2 + 0], pqy1 = pos[(q0 + lrow0 + 8) * 2 + 1];

    float oacc[8][4];
#pragma unroll
    for (int i = 0; i < 8; i++)
#pragma unroll
        for (int j = 0; j < 4; j++) oacc[i][j] = 0.f;
    float lsum0 = 0.f, lsum1 = 0.f;

    float sacc[8][4];

    for (int kt = 0; kt < 32; kt++) {
        const int k0 = kt * 64;
        __syncthreads();   // previous iteration's reads done
        // K tile -> Khi/Klo ; V tile -> transposed Vthi/Vtlo
#pragma unroll
        for (int s = 0; s < 4; s++) {
            int idx = tid + 256 * s;
            int r = idx >> 4, c4 = (idx & 15) * 4;
            float4 kv = *(const float4*)(kb + (size_t)(k0 + r) * 64 + c4);
            *(u32*)&Khi[r * QS + c4]     = pack_hi2(kv.x, kv.y);
            *(u32*)&Khi[r * QS + c4 + 2] = pack_hi2(kv.z, kv.w);
            *(u32*)&Klo[r * QS + c4]     = pack_lo2(kv.x, kv.y);
            *(u32*)&Klo[r * QS + c4 + 2] = pack_lo2(kv.z, kv.w);
            float4 vv = *(const float4*)(vb + (size_t)(k0 + r) * 64 + c4);
            float vvs[4] = {vv.x, vv.y, vv.z, vv.w};
#pragma unroll
            for (int i = 0; i < 4; i++) {
                __nv_bfloat16 h = __float2bfloat16(vvs[i]);
                Vthi[(c4 + i) * QS + r] = h;
                Vtlo[(c4 + i) * QS + r] = __float2bfloat16(vvs[i] - __bfloat162float(h));
            }
        }
        if (tid < 64)
            *(float2*)&pks[tid * 2] = *(const float2*)(pos + (size_t)(k0 + tid) * 2);
        __syncthreads();

        // ---- S = Q K^T (3-term hi/lo) ----
#pragma unroll
        for (int i = 0; i < 8; i++)
#pragma unroll
            for (int j = 0; j < 4; j++) sacc[i][j] = 0.f;

#pragma unroll
        for (int ks = 0; ks < 4; ks++) {
            int abase = lrow0 * QS + ks * 16 + 2 * qc;
            u32 qh0 = *(u32*)&Qhi[abase];
            u32 qh1 = *(u32*)&Qhi[abase + 8 * QS];
            u32 qh2 = *(u32*)&Qhi[abase + 8];
            u32 qh3 = *(u32*)&Qhi[abase + 8 * QS + 8];
            u32 ql0 = *(u32*)&Qlo[abase];
            u32 ql1 = *(u32*)&Qlo[abase + 8 * QS];
            u32 ql2 = *(u32*)&Qlo[abase + 8];
            u32 ql3 = *(u32*)&Qlo[abase + 8 * QS + 8];
#pragma unroll
            for (int nt = 0; nt < 8; nt++) {
                int bbase = (nt * 8 + qr) * QS + ks * 16 + 2 * qc;
                u32 kh0 = *(u32*)&Khi[bbase];
                u32 kh1 = *(u32*)&Khi[bbase + 8];
                u32 kl0 = *(u32*)&Klo[bbase];
                u32 kl1 = *(u32*)&Klo[bbase + 8];
                mma16816(sacc[nt], qh0, qh1, qh2, qh3, kh0, kh1);
                mma16816(sacc[nt], qh0, qh1, qh2, qh3, kl0, kl1);
                mma16816(sacc[nt], ql0, ql1, ql2, ql3, kh0, kh1);
            }
        }

        // ---- softmax (fixed max 8): p = exp2((s/8 - edist)*log2e - 8*log2e) ----
#pragma unroll
        for (int nt = 0; nt < 8; nt++) {
            int cb = nt * 8 + 2 * qc;
            float4 pk4 = *(const float4*)&pks[cb * 2];   // x0,y0,x1,y1
            float dx, dy, e0, e1;
            dx = fabsf(pqx0 - pk4.x); dx = fminf(dx, 1.0f - dx);
            dy = fabsf(pqy0 - pk4.y); dy = fminf(dy, 1.0f - dy);
            e0 = dx * dx + dy * dy;
            dx = fabsf(pqx0 - pk4.z); dx = fminf(dx, 1.0f - dx);
            dy = fabsf(pqy0 - pk4.w); dy = fminf(dy, 1.0f - dy);
            e1 = dx * dx + dy * dy;
            float p0 = exp2f(fmaf(fmaf(sacc[nt][0], 0.125f, -e0), 1.44269504f, -11.54156036f));
            float p1 = exp2f(fmaf(fmaf(sacc[nt][1], 0.125f, -e1), 1.44269504f, -11.54156036f));
            dx = fabsf(pqx1 - pk4.x); dx = fminf(dx, 1.0f - dx);
            dy = fabsf(pqy1 - pk4.y); dy = fminf(dy, 1.0f - dy);
            e0 = dx * dx + dy * dy;
            dx = fabsf(pqx1 - pk4.z); dx = fminf(dx, 1.0f - dx);
            dy = fabsf(pqy1 - pk4.w); dy = fminf(dy, 1.0f - dy);
            e1 = dx * dx + dy * dy;
            float p2 = exp2f(fmaf(fmaf(sacc[nt][2], 0.125f, -e0), 1.44269504f, -11.54156036f));
            float p3 = exp2f(fmaf(fmaf(sacc[nt][3], 0.125f, -e1), 1.44269504f, -11.54156036f));
            lsum0 += p0 + p1;
            lsum1 += p2 + p3;
            sacc[nt][0] = p0; sacc[nt][1] = p1; sacc[nt][2] = p2; sacc[nt][3] = p3;
        }

        // ---- O += P V  (P fragments straight from sacc regs) ----
#pragma unroll
        for (int ks = 0; ks < 4; ks++) {
            u32 ah0 = pack_hi2(sacc[2 * ks][0],     sacc[2 * ks][1]);
            u32 ah1 = pack_hi2(sacc[2 * ks][2],     sacc[2 * ks][3]);
            u32 ah2 = pack_hi2(sacc[2 * ks + 1][0], sacc[2 * ks + 1][1]);
            u32 ah3 = pack_hi2(sacc[2 * ks + 1][2], sacc[2 * ks + 1][3]);
            u32 al0 = pack_lo2(sacc[2 * ks][0],     sacc[2 * ks][1]);
            u32 al1 = pack_lo2(sacc[2 * ks][2],     sacc[2 * ks][3]);
            u32 al2 = pack_lo2(sacc[2 * ks + 1][0], sacc[2 * ks + 1][1]);
            u32 al3 = pack_lo2(sacc[2 * ks + 1][2], sacc[2 * ks + 1][3]);
#pragma unroll
            for (int nt = 0; nt < 8; nt++) {
                int bbase = (nt * 8 + qr) * QS + ks * 16 + 2 * qc;
                u32 vh0 = *(u32*)&Vthi[bbase];
                u32 vh1 = *(u32*)&Vthi[bbase + 8];
                u32 vl0 = *(u32*)&Vtlo[bbase];
                u32 vl1 = *(u32*)&Vtlo[bbase + 8];
                mma16816(oacc[nt], ah0, ah1, ah2, ah3, vh0, vh1);
                mma16816(oacc[nt], ah0, ah1, ah2, ah3, vl0, vl1);
                mma16816(oacc[nt], al0, al1, al2, al3, vh0, vh1);
            }
        }
    }

    // reduce row sums over the 4 lanes of each quad (same qr)
#pragma unroll
    for (int off = 1; off <= 2; off <<= 1) {
        lsum0 += __shfl_xor_sync(0xffffffffu, lsum0, off);
        lsum1 += __shfl_xor_sync(0xffffffffu, lsum1, off);
    }
    float inv0 = 1.0f / lsum0, inv1 = 1.0f / lsum1;

    float* ob = g_att + ((size_t)bi * NN + q0) * DIM + head * 64;
#pragma unroll
    for (int nt = 0; nt < 8; nt++) {
        int cb = nt * 8 + 2 * qc;
        float2 r0 = make_float2(oacc[nt][0] * inv0, oacc[nt][1] * inv0);
        float2 r1 = make_float2(oacc[nt][2] * inv1, oacc[nt][3] * inv1);
        *(float2*)&ob[(size_t)lrow0 * DIM + cb] = r0;
        *(float2*)&ob[(size_t)(lrow0 + 8) * DIM + cb] = r1;
    }
}

// ---------------------------------------------------------------------------
// Kernel 4: output GEMM (scalar FFMA2, 128x128, best measured config).
// ---------------------------------------------------------------------------
__global__ __launch_bounds__(256, 1) void out_gemm_kernel(
    const float* __restrict__ W, const float* __restrict__ bout, float* __restrict__ out)
{
    __shared__ float AsT[16][132];
    __shared__ float Bs[16][132];

    const int tid = threadIdx.x;
    const int tx = tid & 15, ty = tid >> 4;
    const int row0 = blockIdx.y * 128;
    const int col0 = blockIdx.x * 128;

    u64 acc2[8][4];
#pragma unroll
    for (int i = 0; i < 8; i++)
#pragma unroll
        for (int j = 0; j < 4; j++) acc2[i][j] = 0ull;

    for (int k0 = 0; k0 < 512; k0 += 16) {
#pragma unroll
        for (int s = 0; s < 2; s++) {
            int idx = tid + s * 256;
            int r = idx >> 2, c4 = idx & 3;
            float4 va = *(const float4*)(g_att + (size_t)(row0 + r) * 512 + k0 + c4 * 4);
            AsT[c4 * 4 + 0][r] = va.x;
            AsT[c4 * 4 + 1][r] = va.y;
            AsT[c4 * 4 + 2][r] = va.z;
            AsT[c4 * 4 + 3][r] = va.w;
            int kr = idx >> 5, cc = idx & 31;
            *(float4*)&Bs[kr][cc * 4] =
                *(const float4*)(W + (size_t)(k0 + kr) * 512 + col0 + cc * 4);
        }
        __syncthreads();
#pragma unroll
        for (int kk = 0; kk < 16; kk++) {
            float4 a0 = *(float4*)&AsT[kk][ty * 8];
            float4 a1 = *(float4*)&AsT[kk][ty * 8 + 4];
            ulonglong2 b0 = *(ulonglong2*)&Bs[kk][tx * 4];
            ulonglong2 b1 = *(ulonglong2*)&Bs[kk][64 + tx * 4];
            float a[8] = {a0.x, a0.y, a0.z, a0.w, a1.x, a1.y, a1.z, a1.w};
#pragma unroll
            for (int i = 0; i < 8; i++) {
                u64 ad = pack2(a[i], a[i]);
                acc2[i][0] = ffma2(ad, b0.x, acc2[i][0]);
                acc2[i][1] = ffma2(ad, b0.y, acc2[i][1]);
                acc2[i][2] = ffma2(ad, b1.x, acc2[i][2]);
                acc2[i][3] = ffma2(ad, b1.y, acc2[i][3]);
            }
        }
        __syncthreads();
    }

#pragma unroll
    for (int i = 0; i < 8; i++) {
        int m = row0 + ty * 8 + i;
#pragma unroll
        for (int half = 0; half < 2; half++) {
            int c = col0 + half * 64 + tx * 4;
            float4 bv = *(const float4*)(bout + c);
            float2 p0 = unpack2(acc2[i][half * 2 + 0]);
            float2 p1 = unpack2(acc2[i][half * 2 + 1]);
            float4 r;
            r.x = p0.x + bv.x;
            r.y = p0.y + bv.y;
            r.z = p1.x + bv.z;
            r.w = p1.y + bv.w;
            *(float4*)&out[(size_t)m * 512 + c] = r;
        }
    }
}

// ---------------------------------------------------------------------------
extern "C" void kernel_launch(void* const* d_in, const int* in_sizes, int n_in,
                              void* d_out, int out_size)
{
    const float* x    = (const float*)d_in[0];
    const float* pos  = (const float*)d_in[1];
    const float* W_in = (const float*)d_in[2];
    const float* b_in = (const float*)d_in[3];
    const float* qn_w = (const float*)d_in[4];
    const float* qn_b = (const float*)d_in[5];
    const float* kn_w = (const float*)d_in[6];
    const float* kn_b = (const float*)d_in[7];
    const float* W_out= (const float*)d_in[8];
    const float* b_out= (const float*)d_in[9];
    float* out = (float*)d_out;

    cudaFuncSetAttribute(attn_kernel, cudaFuncAttributeMaxDynamicSharedMemorySize,
                         ATTN_SMEM_BYTES);

    qkv_gemm_kernel<<<dim3(12, 32), 256>>>(x, W_in, b_in);
    ln_qk_kernel<<<(2 * BHD * NN) / 8, 256>>>(qn_w, qn_b, kn_w, kn_b);
    attn_kernel<<<dim3(16, 16), 256, ATTN_SMEM_BYTES>>>(pos);
    out_gemm_kernel<<<dim3(4, 32), 256>>>(W_out, b_out, out);
}

// round 6
// speedup vs baseline: 2.2333x; 1.2298x over previous
#include <cuda_runtime.h>
#include <cuda_bf16.h>
#include <math.h>
#include <stdint.h>

#define BB   2
#define NN   2048
#define DIM  512
#define HH   8
#define DD   64
#define BN   (BB*NN)    // 4096
#define BHD  (BB*HH)    // 16

// Scratch (allocation-free)
__device__ float g_q[BHD*NN*DD];
__device__ float g_k[BHD*NN*DD];
__device__ float g_v[BHD*NN*DD];
__device__ float g_att[BN*DIM];

typedef unsigned long long u64;
typedef unsigned int u32;

// ---------------------------------------------------------------------------
// mma.sync bf16 helpers
// ---------------------------------------------------------------------------
__device__ __forceinline__ void mma16816(float* c,
    u32 a0, u32 a1, u32 a2, u32 a3, u32 b0, u32 b1)
{
    asm volatile(
        "mma.sync.aligned.m16n8k16.row.col.f32.bf16.bf16.f32 "
        "{%0,%1,%2,%3}, {%4,%5,%6,%7}, {%8,%9}, {%0,%1,%2,%3};"
        : "+f"(c[0]), "+f"(c[1]), "+f"(c[2]), "+f"(c[3])
        : "r"(a0), "r"(a1), "r"(a2), "r"(a3), "r"(b0), "r"(b1));
}

__device__ __forceinline__ u32 pack_bf(__nv_bfloat16 a, __nv_bfloat16 b) {
    u32 lo = (u32)__bfloat16_as_ushort(a);
    u32 hi = (u32)__bfloat16_as_ushort(b);
    return lo | (hi << 16);
}
__device__ __forceinline__ u32 pack_hi2(float x, float y) {
    return pack_bf(__float2bfloat16(x), __float2bfloat16(y));
}
__device__ __forceinline__ u32 pack_lo2(float x, float y) {
    __nv_bfloat16 hx = __float2bfloat16(x), hy = __float2bfloat16(y);
    return pack_bf(__float2bfloat16(x - __bfloat162float(hx)),
                   __float2bfloat16(y - __bfloat162float(hy)));
}

// ---------------------------------------------------------------------------
// Shared tensor-core GEMM body: C[128 x 128] tile = A[128 x 512] B^T
// A row-major (lda=512), B accessed as B[n][k] = bptr[k*ldb + n].
// 8 warps: wm = w>>2 (two 64-row halves), wn = w&3 (four 32-col strips).
// Each warp: 4 m16-tiles x 4 n8-tiles, 3-term hi/lo accumulate.
// ---------------------------------------------------------------------------
#define GP 72                       // padded row length (bf16 elems)
#define SM_AHI 0
#define SM_ALO (SM_AHI + 128*GP*2)
#define SM_BHI (SM_ALO + 128*GP*2)
#define SM_BLO (SM_BHI + 128*GP*2)
#define GEMM_SMEM_BYTES (SM_BLO + 128*GP*2)

__device__ __forceinline__ void gemm_mma_body(
    const float* __restrict__ aptr,      // + row0*512 already applied
    const float* __restrict__ bptr,      // + col0 already applied
    int ldb, char* smc, float cacc[4][4][4])
{
    __nv_bfloat16* Ahi = (__nv_bfloat16*)(smc + SM_AHI);
    __nv_bfloat16* Alo = (__nv_bfloat16*)(smc + SM_ALO);
    __nv_bfloat16* Bhi = (__nv_bfloat16*)(smc + SM_BHI);
    __nv_bfloat16* Blo = (__nv_bfloat16*)(smc + SM_BLO);

    const int tid = threadIdx.x;
    const int w = tid >> 5, lane = tid & 31;
    const int qr = lane >> 2, qc = lane & 3;
    const int wm = w >> 2, wn = w & 3;

#pragma unroll
    for (int mt = 0; mt < 4; mt++)
#pragma unroll
        for (int nt = 0; nt < 4; nt++)
#pragma unroll
            for (int j = 0; j < 4; j++) cacc[mt][nt][j] = 0.f;

    for (int c = 0; c < 8; c++) {
        const int k0 = c * 64;
        if (c) __syncthreads();
        // ---- A tile 128x64 -> Ahi/Alo ----
#pragma unroll
        for (int s = 0; s < 8; s++) {
            int idx = tid + 256 * s;
            int r = idx >> 4, c4 = (idx & 15) * 4;
            float4 v = *(const float4*)(aptr + (size_t)r * 512 + k0 + c4);
            *(u32*)&Ahi[r * GP + c4]     = pack_hi2(v.x, v.y);
            *(u32*)&Ahi[r * GP + c4 + 2] = pack_hi2(v.z, v.w);
            *(u32*)&Alo[r * GP + c4]     = pack_lo2(v.x, v.y);
            *(u32*)&Alo[r * GP + c4 + 2] = pack_lo2(v.z, v.w);
        }
        // ---- B tile: B[n][k] = bptr[k*ldb + n], n=0..127, k=k0..k0+63 ----
#pragma unroll
        for (int s = 0; s < 16; s++) {
            int p = tid + 256 * s;
            int n = p & 127, kk = (p >> 7) * 2;
            float b0 = bptr[(size_t)(k0 + kk) * ldb + n];
            float b1 = bptr[(size_t)(k0 + kk + 1) * ldb + n];
            *(u32*)&Bhi[n * GP + kk] = pack_hi2(b0, b1);
            *(u32*)&Blo[n * GP + kk] = pack_lo2(b0, b1);
        }
        __syncthreads();

#pragma unroll
        for (int ks = 0; ks < 4; ks++) {
            u32 bh[4][2], bl[4][2];
#pragma unroll
            for (int nt = 0; nt < 4; nt++) {
                int bbase = (wn * 32 + nt * 8 + qr) * GP + ks * 16 + 2 * qc;
                bh[nt][0] = *(u32*)&Bhi[bbase];
                bh[nt][1] = *(u32*)&Bhi[bbase + 8];
                bl[nt][0] = *(u32*)&Blo[bbase];
                bl[nt][1] = *(u32*)&Blo[bbase + 8];
            }
#pragma unroll
            for (int mt = 0; mt < 4; mt++) {
                int abase = (wm * 64 + mt * 16 + qr) * GP + ks * 16 + 2 * qc;
                u32 ah0 = *(u32*)&Ahi[abase];
                u32 ah1 = *(u32*)&Ahi[abase + 8 * GP];
                u32 ah2 = *(u32*)&Ahi[abase + 8];
                u32 ah3 = *(u32*)&Ahi[abase + 8 * GP + 8];
                u32 al0 = *(u32*)&Alo[abase];
                u32 al1 = *(u32*)&Alo[abase + 8 * GP];
                u32 al2 = *(u32*)&Alo[abase + 8];
                u32 al3 = *(u32*)&Alo[abase + 8 * GP + 8];
#pragma unroll
                for (int nt = 0; nt < 4; nt++) {
                    mma16816(cacc[mt][nt], ah0, ah1, ah2, ah3, bh[nt][0], bh[nt][1]);
                    mma16816(cacc[mt][nt], ah0, ah1, ah2, ah3, bl[nt][0], bl[nt][1]);
                    mma16816(cacc[mt][nt], al0, al1, al2, al3, bh[nt][0], bh[nt][1]);
                }
            }
        }
    }
}

// ---------------------------------------------------------------------------
// Kernel 1: QKV GEMM (tensor core). C[4096,1536] = x @ W_in + b_in -> q/k/v
// ---------------------------------------------------------------------------
__global__ __launch_bounds__(256, 2) void qkv_gemm_kernel(
    const float* __restrict__ x, const float* __restrict__ W,
    const float* __restrict__ bin)
{
    extern __shared__ char smc[];
    const int row0 = blockIdx.y * 128;
    const int col0 = blockIdx.x * 128;
    const int lane = threadIdx.x & 31;
    const int w = threadIdx.x >> 5;
    const int qr = lane >> 2, qc = lane & 3;
    const int wm = w >> 2, wn = w & 3;

    float cacc[4][4][4];
    gemm_mma_body(x + (size_t)row0 * 512, W + col0, 1536, smc, cacc);

#pragma unroll
    for (int mt = 0; mt < 4; mt++) {
        int grow = row0 + wm * 64 + mt * 16 + qr;
        int bi = grow >> 11, ni = grow & 2047;
#pragma unroll
        for (int nt = 0; nt < 4; nt++) {
            int c0 = col0 + wn * 32 + nt * 8 + 2 * qc;
            int three = c0 >> 9;
            int head  = (c0 >> 6) & 7;
            float* dst = (three == 0) ? g_q : (three == 1) ? g_k : g_v;
            float* base = dst + (((size_t)bi * HH + head) * NN) * DD + (c0 & 63);
            float2 bv = *(const float2*)(bin + c0);
            float2 r0 = make_float2(cacc[mt][nt][0] + bv.x, cacc[mt][nt][1] + bv.y);
            float2 r1 = make_float2(cacc[mt][nt][2] + bv.x, cacc[mt][nt][3] + bv.y);
            *(float2*)&base[(size_t)ni * 64] = r0;
            *(float2*)&base[(size_t)(ni + 8) * 64] = r1;
        }
    }
}

// ---------------------------------------------------------------------------
// Kernel 2: per-head LayerNorm on q and k rows (d=64). One warp per row.
// ---------------------------------------------------------------------------
__global__ void ln_qk_kernel(const float* __restrict__ qn_w, const float* __restrict__ qn_b,
                             const float* __restrict__ kn_w, const float* __restrict__ kn_b)
{
    const int ROWS = BHD * NN;
    int gid = blockIdx.x * 8 + (threadIdx.x >> 5);
    int lane = threadIdx.x & 31;
    if (gid >= 2 * ROWS) return;
    bool isq = gid < ROWS;
    int r = isq ? gid : gid - ROWS;
    float* buf = isq ? g_q : g_k;
    const float* w = isq ? qn_w : kn_w;
    const float* bb = isq ? qn_b : kn_b;

    float x0 = buf[(size_t)r * 64 + lane];
    float x1 = buf[(size_t)r * 64 + 32 + lane];
    float s = x0 + x1;
#pragma unroll
    for (int off = 16; off >= 1; off >>= 1) s += __shfl_xor_sync(0xffffffffu, s, off);
    float mu = s * (1.0f / 64.0f);
    float d0 = x0 - mu, d1 = x1 - mu;
    float v = d0 * d0 + d1 * d1;
#pragma unroll
    for (int off = 16; off >= 1; off >>= 1) v += __shfl_xor_sync(0xffffffffu, v, off);
    float inv = rsqrtf(v * (1.0f / 64.0f) + 1e-5f);
    buf[(size_t)r * 64 + lane]      = d0 * inv * w[lane] + bb[lane];
    buf[(size_t)r * 64 + 32 + lane] = d1 * inv * w[lane + 32] + bb[lane + 32];
}

// ---------------------------------------------------------------------------
// Kernel 3: flash attention via mma.sync bf16 hi/lo (3-term), fixed-max softmax.
// (unchanged from R5 — verified)
// ---------------------------------------------------------------------------
#define QS 72
#define SM_QHI   0
#define SM_QLO   (SM_QHI  + 128*QS*2)
#define SM_KHI   (SM_QLO  + 128*QS*2)
#define SM_KLO   (SM_KHI  + 64*QS*2)
#define SM_VTHI  (SM_KLO  + 64*QS*2)
#define SM_VTLO  (SM_VTHI + 64*QS*2)
#define SM_PK    (SM_VTLO + 64*QS*2)
#define ATTN_SMEM_BYTES (SM_PK + 64*2*4)

__global__ __launch_bounds__(256, 2) void attn_kernel(const float* __restrict__ pos)
{
    extern __shared__ char smc[];
    __nv_bfloat16* Qhi  = (__nv_bfloat16*)(smc + SM_QHI);
    __nv_bfloat16* Qlo  = (__nv_bfloat16*)(smc + SM_QLO);
    __nv_bfloat16* Khi  = (__nv_bfloat16*)(smc + SM_KHI);
    __nv_bfloat16* Klo  = (__nv_bfloat16*)(smc + SM_KLO);
    __nv_bfloat16* Vthi = (__nv_bfloat16*)(smc + SM_VTHI);
    __nv_bfloat16* Vtlo = (__nv_bfloat16*)(smc + SM_VTLO);
    float* pks = (float*)(smc + SM_PK);

    const int tid = threadIdx.x;
    const int w = tid >> 5, lane = tid & 31;
    const int qr = lane >> 2, qc = lane & 3;
    const int q0 = blockIdx.x * 128;
    const int bh = blockIdx.y;
    const int bi = bh >> 3, head = bh & 7;

    const float* qb = g_q + (size_t)bh * NN * DD;
    const float* kb = g_k + (size_t)bh * NN * DD;
    const float* vb = g_v + (size_t)bh * NN * DD;

#pragma unroll
    for (int s = 0; s < 8; s++) {
        int idx = tid + 256 * s;
        int r = idx >> 4, c4 = (idx & 15) * 4;
        float4 v = *(const float4*)(qb + (size_t)(q0 + r) * 64 + c4);
        *(u32*)&Qhi[r * QS + c4]     = pack_hi2(v.x, v.y);
        *(u32*)&Qhi[r * QS + c4 + 2] = pack_hi2(v.z, v.w);
        *(u32*)&Qlo[r * QS + c4]     = pack_lo2(v.x, v.y);
        *(u32*)&Qlo[r * QS + c4 + 2] = pack_lo2(v.z, v.w);
    }

    const int lrow0 = w * 16 + qr;
    float pqx0 = pos[(q0 + lrow0) * 2 + 0], pqy0 = pos[(q0 + lrow0) * 2 + 1];
    float pqx1 = pos[(q0 + lrow0 + 8) * 2 + 0], pqy1 = pos[(q0 + lrow0 + 8) * 2 + 1];

    float oacc[8][4];
#pragma unroll
    for (int i = 0; i < 8; i++)
#pragma unroll
        for (int j = 0; j < 4; j++) oacc[i][j] = 0.f;
    float lsum0 = 0.f, lsum1 = 0.f;

    float sacc[8][4];

    for (int kt = 0; kt < 32; kt++) {
        const int k0 = kt * 64;
        __syncthreads();
#pragma unroll
        for (int s = 0; s < 4; s++) {
            int idx = tid + 256 * s;
            int r = idx >> 4, c4 = (idx & 15) * 4;
            float4 kv = *(const float4*)(kb + (size_t)(k0 + r) * 64 + c4);
            *(u32*)&Khi[r * QS + c4]     = pack_hi2(kv.x, kv.y);
            *(u32*)&Khi[r * QS + c4 + 2] = pack_hi2(kv.z, kv.w);
            *(u32*)&Klo[r * QS + c4]     = pack_lo2(kv.x, kv.y);
            *(u32*)&Klo[r * QS + c4 + 2] = pack_lo2(kv.z, kv.w);
            float4 vv = *(const float4*)(vb + (size_t)(k0 + r) * 64 + c4);
            float vvs[4] = {vv.x, vv.y, vv.z, vv.w};
#pragma unroll
            for (int i = 0; i < 4; i++) {
                __nv_bfloat16 h = __float2bfloat16(vvs[i]);
                Vthi[(c4 + i) * QS + r] = h;
                Vtlo[(c4 + i) * QS + r] = __float2bfloat16(vvs[i] - __bfloat162float(h));
            }
        }
        if (tid < 64)
            *(float2*)&pks[tid * 2] = *(const float2*)(pos + (size_t)(k0 + tid) * 2);
        __syncthreads();

#pragma unroll
        for (int i = 0; i < 8; i++)
#pragma unroll
            for (int j = 0; j < 4; j++) sacc[i][j] = 0.f;

#pragma unroll
        for (int ks = 0; ks < 4; ks++) {
            int abase = lrow0 * QS + ks * 16 + 2 * qc;
            u32 qh0 = *(u32*)&Qhi[abase];
            u32 qh1 = *(u32*)&Qhi[abase + 8 * QS];
            u32 qh2 = *(u32*)&Qhi[abase + 8];
            u32 qh3 = *(u32*)&Qhi[abase + 8 * QS + 8];
            u32 ql0 = *(u32*)&Qlo[abase];
            u32 ql1 = *(u32*)&Qlo[abase + 8 * QS];
            u32 ql2 = *(u32*)&Qlo[abase + 8];
            u32 ql3 = *(u32*)&Qlo[abase + 8 * QS + 8];
#pragma unroll
            for (int nt = 0; nt < 8; nt++) {
                int bbase = (nt * 8 + qr) * QS + ks * 16 + 2 * qc;
                u32 kh0 = *(u32*)&Khi[bbase];
                u32 kh1 = *(u32*)&Khi[bbase + 8];
                u32 kl0 = *(u32*)&Klo[bbase];
                u32 kl1 = *(u32*)&Klo[bbase + 8];
                mma16816(sacc[nt], qh0, qh1, qh2, qh3, kh0, kh1);
                mma16816(sacc[nt], qh0, qh1, qh2, qh3, kl0, kl1);
                mma16816(sacc[nt], ql0, ql1, ql2, ql3, kh0, kh1);
            }
        }

#pragma unroll
        for (int nt = 0; nt < 8; nt++) {
            int cb = nt * 8 + 2 * qc;
            float4 pk4 = *(const float4*)&pks[cb * 2];
            float dx, dy, e0, e1;
            dx = fabsf(pqx0 - pk4.x); dx = fminf(dx, 1.0f - dx);
            dy = fabsf(pqy0 - pk4.y); dy = fminf(dy, 1.0f - dy);
            e0 = dx * dx + dy * dy;
            dx = fabsf(pqx0 - pk4.z); dx = fminf(dx, 1.0f - dx);
            dy = fabsf(pqy0 - pk4.w); dy = fminf(dy, 1.0f - dy);
            e1 = dx * dx + dy * dy;
            float p0 = exp2f(fmaf(fmaf(sacc[nt][0], 0.125f, -e0), 1.44269504f, -11.54156036f));
            float p1 = exp2f(fmaf(fmaf(sacc[nt][1], 0.125f, -e1), 1.44269504f, -11.54156036f));
            dx = fabsf(pqx1 - pk4.x); dx = fminf(dx, 1.0f - dx);
            dy = fabsf(pqy1 - pk4.y); dy = fminf(dy, 1.0f - dy);
            e0 = dx * dx + dy * dy;
            dx = fabsf(pqx1 - pk4.z); dx = fminf(dx, 1.0f - dx);
            dy = fabsf(pqy1 - pk4.w); dy = fminf(dy, 1.0f - dy);
            e1 = dx * dx + dy * dy;
            float p2 = exp2f(fmaf(fmaf(sacc[nt][2], 0.125f, -e0), 1.44269504f, -11.54156036f));
            float p3 = exp2f(fmaf(fmaf(sacc[nt][3], 0.125f, -e1), 1.44269504f, -11.54156036f));
            lsum0 += p0 + p1;
            lsum1 += p2 + p3;
            sacc[nt][0] = p0; sacc[nt][1] = p1; sacc[nt][2] = p2; sacc[nt][3] = p3;
        }

#pragma unroll
        for (int ks = 0; ks < 4; ks++) {
            u32 ah0 = pack_hi2(sacc[2 * ks][0],     sacc[2 * ks][1]);
            u32 ah1 = pack_hi2(sacc[2 * ks][2],     sacc[2 * ks][3]);
            u32 ah2 = pack_hi2(sacc[2 * ks + 1][0], sacc[2 * ks + 1][1]);
            u32 ah3 = pack_hi2(sacc[2 * ks + 1][2], sacc[2 * ks + 1][3]);
            u32 al0 = pack_lo2(sacc[2 * ks][0],     sacc[2 * ks][1]);
            u32 al1 = pack_lo2(sacc[2 * ks][2],     sacc[2 * ks][3]);
            u32 al2 = pack_lo2(sacc[2 * ks + 1][0], sacc[2 * ks + 1][1]);
            u32 al3 = pack_lo2(sacc[2 * ks + 1][2], sacc[2 * ks + 1][3]);
#pragma unroll
            for (int nt = 0; nt < 8; nt++) {
                int bbase = (nt * 8 + qr) * QS + ks * 16 + 2 * qc;
                u32 vh0 = *(u32*)&Vthi[bbase];
                u32 vh1 = *(u32*)&Vthi[bbase + 8];
                u32 vl0 = *(u32*)&Vtlo[bbase];
                u32 vl1 = *(u32*)&Vtlo[bbase + 8];
                mma16816(oacc[nt], ah0, ah1, ah2, ah3, vh0, vh1);
                mma16816(oacc[nt], ah0, ah1, ah2, ah3, vl0, vl1);
                mma16816(oacc[nt], al0, al1, al2, al3, vh0, vh1);
            }
        }
    }

#pragma unroll
    for (int off = 1; off <= 2; off <<= 1) {
        lsum0 += __shfl_xor_sync(0xffffffffu, lsum0, off);
        lsum1 += __shfl_xor_sync(0xffffffffu, lsum1, off);
    }
    float inv0 = 1.0f / lsum0, inv1 = 1.0f / lsum1;

    float* ob = g_att + ((size_t)bi * NN + q0) * DIM + head * 64;
#pragma unroll
    for (int nt = 0; nt < 8; nt++) {
        int cb = nt * 8 + 2 * qc;
        float2 r0 = make_float2(oacc[nt][0] * inv0, oacc[nt][1] * inv0);
        float2 r1 = make_float2(oacc[nt][2] * inv1, oacc[nt][3] * inv1);
        *(float2*)&ob[(size_t)lrow0 * DIM + cb] = r0;
        *(float2*)&ob[(size_t)(lrow0 + 8) * DIM + cb] = r1;
    }
}

// ---------------------------------------------------------------------------
// Kernel 4: output GEMM (tensor core). out[4096,512] = g_att @ W_out + b_out
// ---------------------------------------------------------------------------
__global__ __launch_bounds__(256, 2) void out_gemm_kernel(
    const float* __restrict__ W, const float* __restrict__ bout, float* __restrict__ out)
{
    extern __shared__ char smc[];
    const int row0 = blockIdx.y * 128;
    const int col0 = blockIdx.x * 128;
    const int lane = threadIdx.x & 31;
    const int w = threadIdx.x >> 5;
    const int qr = lane >> 2, qc = lane & 3;
    const int wm = w >> 2, wn = w & 3;

    float cacc[4][4][4];
    gemm_mma_body(g_att + (size_t)row0 * 512, W + col0, 512, smc, cacc);

#pragma unroll
    for (int mt = 0; mt < 4; mt++) {
        int grow = row0 + wm * 64 + mt * 16 + qr;
#pragma unroll
        for (int nt = 0; nt < 4; nt++) {
            int c0 = col0 + wn * 32 + nt * 8 + 2 * qc;
            float2 bv = *(const float2*)(bout + c0);
            float2 r0 = make_float2(cacc[mt][nt][0] + bv.x, cacc[mt][nt][1] + bv.y);
            float2 r1 = make_float2(cacc[mt][nt][2] + bv.x, cacc[mt][nt][3] + bv.y);
            *(float2*)&out[(size_t)grow * 512 + c0] = r0;
            *(float2*)&out[(size_t)(grow + 8) * 512 + c0] = r1;
        }
    }
}

// ---------------------------------------------------------------------------
extern "C" void kernel_launch(void* const* d_in, const int* in_sizes, int n_in,
                              void* d_out, int out_size)
{
    const float* x    = (const float*)d_in[0];
    const float* pos  = (const float*)d_in[1];
    const float* W_in = (const float*)d_in[2];
    const float* b_in = (const float*)d_in[3];
    const float* qn_w = (const float*)d_in[4];
    const float* qn_b = (const float*)d_in[5];
    const float* kn_w = (const float*)d_in[6];
    const float* kn_b = (const float*)d_in[7];
    const float* W_out= (const float*)d_in[8];
    const float* b_out= (const float*)d_in[9];
    float* out = (float*)d_out;

    cudaFuncSetAttribute(qkv_gemm_kernel, cudaFuncAttributeMaxDynamicSharedMemorySize, GEMM_SMEM_BYTES);
    cudaFuncSetAttribute(out_gemm_kernel, cudaFuncAttributeMaxDynamicSharedMemorySize, GEMM_SMEM_BYTES);
    cudaFuncSetAttribute(attn_kernel, cudaFuncAttributeMaxDynamicSharedMemorySize, ATTN_SMEM_BYTES);

    qkv_gemm_kernel<<<dim3(12, 32), 256, GEMM_SMEM_BYTES>>>(x, W_in, b_in);
    ln_qk_kernel<<<(2 * BHD * NN) / 8, 256>>>(qn_w, qn_b, kn_w, kn_b);
    attn_kernel<<<dim3(16, 16), 256, ATTN_SMEM_BYTES>>>(pos);
    out_gemm_kernel<<<dim3(4, 32), 256, GEMM_SMEM_BYTES>>>(W_out, b_out, out);
}

// round 7
// speedup vs baseline: 2.5989x; 1.1637x over previous
#include <cuda_runtime.h>
#include <cuda_bf16.h>
#include <math.h>
#include <stdint.h>

#define BB   2
#define NN   2048
#define DIM  512
#define HH   8
#define DD   64
#define BN   (BB*NN)    // 4096
#define BHD  (BB*HH)    // 16

typedef unsigned long long u64;
typedef unsigned int u32;

// fp32 scratch (qkv output; q,k consumed by LN, v by transpose)
__device__ float g_q[BHD*NN*DD];
__device__ float g_k[BHD*NN*DD];
__device__ float g_v[BHD*NN*DD];

// bf16 hi/lo scratch
__device__ __nv_bfloat16 g_xh[BN*DIM],    g_xl[BN*DIM];
__device__ __nv_bfloat16 g_winh[1536*512], g_winl[1536*512];   // [n][k]
__device__ __nv_bfloat16 g_wouth[512*512], g_woutl[512*512];   // [n][k]
__device__ __nv_bfloat16 g_qh[BHD*NN*DD], g_ql[BHD*NN*DD];
__device__ __nv_bfloat16 g_kh[BHD*NN*DD], g_kl[BHD*NN*DD];
__device__ __nv_bfloat16 g_vth[BHD*DD*NN], g_vtl[BHD*DD*NN];   // [bh][d][n]
__device__ __nv_bfloat16 g_atth[BN*DIM],  g_attl[BN*DIM];

// ---------------------------------------------------------------------------
// helpers
// ---------------------------------------------------------------------------
__device__ __forceinline__ void mma16816(float* c,
    u32 a0, u32 a1, u32 a2, u32 a3, u32 b0, u32 b1)
{
    asm volatile(
        "mma.sync.aligned.m16n8k16.row.col.f32.bf16.bf16.f32 "
        "{%0,%1,%2,%3}, {%4,%5,%6,%7}, {%8,%9}, {%0,%1,%2,%3};"
        : "+f"(c[0]), "+f"(c[1]), "+f"(c[2]), "+f"(c[3])
        : "r"(a0), "r"(a1), "r"(a2), "r"(a3), "r"(b0), "r"(b1));
}
__device__ __forceinline__ u32 pack_bf(__nv_bfloat16 a, __nv_bfloat16 b) {
    return (u32)__bfloat16_as_ushort(a) | ((u32)__bfloat16_as_ushort(b) << 16);
}
__device__ __forceinline__ u32 pack_hi2(float x, float y) {
    return pack_bf(__float2bfloat16(x), __float2bfloat16(y));
}
__device__ __forceinline__ u32 pack_lo2(float x, float y) {
    __nv_bfloat16 hx = __float2bfloat16(x), hy = __float2bfloat16(y);
    return pack_bf(__float2bfloat16(x - __bfloat162float(hx)),
                   __float2bfloat16(y - __bfloat162float(hy)));
}

// ---------------------------------------------------------------------------
// prep: x -> bf16 hi/lo (row-major)
// ---------------------------------------------------------------------------
__global__ void prep_x_kernel(const float* __restrict__ x) {
    int idx = blockIdx.x * 256 + threadIdx.x;       // one float4
    float4 v = ((const float4*)x)[idx];
    u64 h = (u64)pack_hi2(v.x, v.y) | ((u64)pack_hi2(v.z, v.w) << 32);
    u64 l = (u64)pack_lo2(v.x, v.y) | ((u64)pack_lo2(v.z, v.w) << 32);
    *(u64*)&g_xh[idx * 4] = h;
    *(u64*)&g_xl[idx * 4] = l;
}

// ---------------------------------------------------------------------------
// prep: W[k][n] (row-major, ld=N) -> Wt[n][512] bf16 hi/lo (transposed)
// ---------------------------------------------------------------------------
__global__ void prep_wt_kernel(const float* __restrict__ src,
                               __nv_bfloat16* __restrict__ dsth,
                               __nv_bfloat16* __restrict__ dstl, int N)
{
    __shared__ float t[32][33];
    int n0 = blockIdx.x * 32, k0 = blockIdx.y * 32;
    int tx = threadIdx.x, ty = threadIdx.y;   // (32, 8)
#pragma unroll
    for (int i = 0; i < 4; i++)
        t[ty + 8 * i][tx] = src[(size_t)(k0 + ty + 8 * i) * N + n0 + tx];
    __syncthreads();
#pragma unroll
    for (int i = 0; i < 4; i++) {
        int n = n0 + ty + 8 * i;
        float v = t[tx][ty + 8 * i];
        __nv_bfloat16 h = __float2bfloat16(v);
        dsth[(size_t)n * 512 + k0 + tx] = h;
        dstl[(size_t)n * 512 + k0 + tx] = __float2bfloat16(v - __bfloat162float(h));
    }
}

// ---------------------------------------------------------------------------
// Tensor-core GEMM body on pre-converted bf16: C[128x128] = A[128x512] Bt^T
// A h/l row-major [m][512]; Bt h/l [n][512]. Copy tiles -> padded smem -> mma.
// ---------------------------------------------------------------------------
#define GP 72
#define SM_AHI 0
#define SM_ALO (SM_AHI + 128*GP*2)
#define SM_BHI (SM_ALO + 128*GP*2)
#define SM_BLO (SM_BHI + 128*GP*2)
#define GEMM_SMEM_BYTES (SM_BLO + 128*GP*2)

__device__ __forceinline__ void gemm_mma_body_bf16(
    const __nv_bfloat16* __restrict__ ah, const __nv_bfloat16* __restrict__ al,
    const __nv_bfloat16* __restrict__ bth, const __nv_bfloat16* __restrict__ btl,
    char* smc, float cacc[4][4][4])
{
    __nv_bfloat16* Ahi = (__nv_bfloat16*)(smc + SM_AHI);
    __nv_bfloat16* Alo = (__nv_bfloat16*)(smc + SM_ALO);
    __nv_bfloat16* Bhi = (__nv_bfloat16*)(smc + SM_BHI);
    __nv_bfloat16* Blo = (__nv_bfloat16*)(smc + SM_BLO);

    const int tid = threadIdx.x;
    const int w = tid >> 5, lane = tid & 31;
    const int qr = lane >> 2, qc = lane & 3;
    const int wm = w >> 2, wn = w & 3;

#pragma unroll
    for (int mt = 0; mt < 4; mt++)
#pragma unroll
        for (int nt = 0; nt < 4; nt++)
#pragma unroll
            for (int j = 0; j < 4; j++) cacc[mt][nt][j] = 0.f;

    for (int c = 0; c < 8; c++) {
        const int k0 = c * 64;
        if (c) __syncthreads();
#pragma unroll
        for (int s = 0; s < 4; s++) {
            int idx = tid + 256 * s;
            int r = idx >> 3, seg = (idx & 7) * 8;
            *(uint4*)&Ahi[r * GP + seg] = *(const uint4*)&ah[(size_t)r * 512 + k0 + seg];
            *(uint4*)&Alo[r * GP + seg] = *(const uint4*)&al[(size_t)r * 512 + k0 + seg];
            *(uint4*)&Bhi[r * GP + seg] = *(const uint4*)&bth[(size_t)r * 512 + k0 + seg];
            *(uint4*)&Blo[r * GP + seg] = *(const uint4*)&btl[(size_t)r * 512 + k0 + seg];
        }
        __syncthreads();

#pragma unroll
        for (int ks = 0; ks < 4; ks++) {
            u32 bh[4][2], bl[4][2];
#pragma unroll
            for (int nt = 0; nt < 4; nt++) {
                int bbase = (wn * 32 + nt * 8 + qr) * GP + ks * 16 + 2 * qc;
                bh[nt][0] = *(u32*)&Bhi[bbase];
                bh[nt][1] = *(u32*)&Bhi[bbase + 8];
                bl[nt][0] = *(u32*)&Blo[bbase];
                bl[nt][1] = *(u32*)&Blo[bbase + 8];
            }
#pragma unroll
            for (int mt = 0; mt < 4; mt++) {
                int abase = (wm * 64 + mt * 16 + qr) * GP + ks * 16 + 2 * qc;
                u32 ah0 = *(u32*)&Ahi[abase];
                u32 ah1 = *(u32*)&Ahi[abase + 8 * GP];
                u32 ah2 = *(u32*)&Ahi[abase + 8];
                u32 ah3 = *(u32*)&Ahi[abase + 8 * GP + 8];
                u32 al0 = *(u32*)&Alo[abase];
                u32 al1 = *(u32*)&Alo[abase + 8 * GP];
                u32 al2 = *(u32*)&Alo[abase + 8];
                u32 al3 = *(u32*)&Alo[abase + 8 * GP + 8];
#pragma unroll
                for (int nt = 0; nt < 4; nt++) {
                    mma16816(cacc[mt][nt], ah0, ah1, ah2, ah3, bh[nt][0], bh[nt][1]);
                    mma16816(cacc[mt][nt], ah0, ah1, ah2, ah3, bl[nt][0], bl[nt][1]);
                    mma16816(cacc[mt][nt], al0, al1, al2, al3, bh[nt][0], bh[nt][1]);
                }
            }
        }
    }
}

// ---------------------------------------------------------------------------
// Kernel: QKV GEMM -> q/k/v fp32 scatter
// ---------------------------------------------------------------------------
__global__ __launch_bounds__(256, 2) void qkv_gemm_kernel(const float* __restrict__ bin)
{
    extern __shared__ char smc[];
    const int row0 = blockIdx.y * 128;
    const int col0 = blockIdx.x * 128;
    const int lane = threadIdx.x & 31;
    const int w = threadIdx.x >> 5;
    const int qr = lane >> 2, qc = lane & 3;
    const int wm = w >> 2, wn = w & 3;

    float cacc[4][4][4];
    gemm_mma_body_bf16(g_xh + (size_t)row0 * 512, g_xl + (size_t)row0 * 512,
                       g_winh + (size_t)col0 * 512, g_winl + (size_t)col0 * 512,
                       smc, cacc);

#pragma unroll
    for (int mt = 0; mt < 4; mt++) {
        int grow = row0 + wm * 64 + mt * 16 + qr;
        int bi = grow >> 11, ni = grow & 2047;
#pragma unroll
        for (int nt = 0; nt < 4; nt++) {
            int c0 = col0 + wn * 32 + nt * 8 + 2 * qc;
            int three = c0 >> 9;
            int head  = (c0 >> 6) & 7;
            float* dst = (three == 0) ? g_q : (three == 1) ? g_k : g_v;
            float* base = dst + (((size_t)bi * HH + head) * NN) * DD + (c0 & 63);
            float2 bv = *(const float2*)(bin + c0);
            float2 r0 = make_float2(cacc[mt][nt][0] + bv.x, cacc[mt][nt][1] + bv.y);
            float2 r1 = make_float2(cacc[mt][nt][2] + bv.x, cacc[mt][nt][3] + bv.y);
            *(float2*)&base[(size_t)ni * 64] = r0;
            *(float2*)&base[(size_t)(ni + 8) * 64] = r1;
        }
    }
}

// ---------------------------------------------------------------------------
// Kernel: LayerNorm q,k -> bf16 hi/lo
// ---------------------------------------------------------------------------
__global__ void ln_qk_kernel(const float* __restrict__ qn_w, const float* __restrict__ qn_b,
                             const float* __restrict__ kn_w, const float* __restrict__ kn_b)
{
    const int ROWS = BHD * NN;
    int gid = blockIdx.x * 8 + (threadIdx.x >> 5);
    int lane = threadIdx.x & 31;
    if (gid >= 2 * ROWS) return;
    bool isq = gid < ROWS;
    int r = isq ? gid : gid - ROWS;
    const float* buf = isq ? g_q : g_k;
    __nv_bfloat16* oh = isq ? g_qh : g_kh;
    __nv_bfloat16* ol = isq ? g_ql : g_kl;
    const float* w = isq ? qn_w : kn_w;
    const float* bb = isq ? qn_b : kn_b;

    float x0 = buf[(size_t)r * 64 + lane];
    float x1 = buf[(size_t)r * 64 + 32 + lane];
    float s = x0 + x1;
#pragma unroll
    for (int off = 16; off >= 1; off >>= 1) s += __shfl_xor_sync(0xffffffffu, s, off);
    float mu = s * (1.0f / 64.0f);
    float d0 = x0 - mu, d1 = x1 - mu;
    float v = d0 * d0 + d1 * d1;
#pragma unroll
    for (int off = 16; off >= 1; off >>= 1) v += __shfl_xor_sync(0xffffffffu, v, off);
    float inv = rsqrtf(v * (1.0f / 64.0f) + 1e-5f);
    float y0 = d0 * inv * w[lane] + bb[lane];
    float y1 = d1 * inv * w[lane + 32] + bb[lane + 32];
    __nv_bfloat16 h0 = __float2bfloat16(y0);
    __nv_bfloat16 h1 = __float2bfloat16(y1);
    oh[(size_t)r * 64 + lane]      = h0;
    oh[(size_t)r * 64 + 32 + lane] = h1;
    ol[(size_t)r * 64 + lane]      = __float2bfloat16(y0 - __bfloat162float(h0));
    ol[(size_t)r * 64 + 32 + lane] = __float2bfloat16(y1 - __bfloat162float(h1));
}

// ---------------------------------------------------------------------------
// Kernel: v [bh][n][64] fp32 -> vt [bh][d][n] bf16 hi/lo
// ---------------------------------------------------------------------------
__global__ void vt_kernel()
{
    __shared__ float ts[64][65];
    int bh = blockIdx.y;
    int n0 = blockIdx.x * 64;
    int tid = threadIdx.x;
    const float* vb = g_v + (size_t)bh * NN * DD + (size_t)n0 * 64;

#pragma unroll
    for (int i = 0; i < 4; i++) {
        int f4 = tid + 256 * i;
        int r = f4 >> 4, c4 = (f4 & 15) * 4;
        float4 v = *(const float4*)(vb + (size_t)r * 64 + c4);
        ts[r][c4 + 0] = v.x; ts[r][c4 + 1] = v.y;
        ts[r][c4 + 2] = v.z; ts[r][c4 + 3] = v.w;
    }
    __syncthreads();

    int d = tid >> 2, ns = (tid & 3) * 16;
    __nv_bfloat16* oh = g_vth + (size_t)bh * DD * NN + (size_t)d * NN + n0 + ns;
    __nv_bfloat16* ol = g_vtl + (size_t)bh * DD * NN + (size_t)d * NN + n0 + ns;
#pragma unroll
    for (int j = 0; j < 8; j++) {
        float a = ts[ns + 2 * j][d], b = ts[ns + 2 * j + 1][d];
        *(u32*)&oh[2 * j] = pack_hi2(a, b);
        *(u32*)&ol[2 * j] = pack_lo2(a, b);
    }
}

// ---------------------------------------------------------------------------
// Kernel: flash attention (mma.sync, pre-converted bf16, fixed-max softmax)
// ---------------------------------------------------------------------------
#define QS 72
#define SM_QHI   0
#define SM_QLO   (SM_QHI  + 128*QS*2)
#define SM_KHI   (SM_QLO  + 128*QS*2)
#define SM_KLO   (SM_KHI  + 64*QS*2)
#define SM_VTHI  (SM_KLO  + 64*QS*2)
#define SM_VTLO  (SM_VTHI + 64*QS*2)
#define SM_PK    (SM_VTLO + 64*QS*2)
#define ATTN_SMEM_BYTES (SM_PK + 64*2*4)

__global__ __launch_bounds__(256, 2) void attn_kernel(const float* __restrict__ pos)
{
    extern __shared__ char smc[];
    __nv_bfloat16* Qhi  = (__nv_bfloat16*)(smc + SM_QHI);
    __nv_bfloat16* Qlo  = (__nv_bfloat16*)(smc + SM_QLO);
    __nv_bfloat16* Khi  = (__nv_bfloat16*)(smc + SM_KHI);
    __nv_bfloat16* Klo  = (__nv_bfloat16*)(smc + SM_KLO);
    __nv_bfloat16* Vthi = (__nv_bfloat16*)(smc + SM_VTHI);
    __nv_bfloat16* Vtlo = (__nv_bfloat16*)(smc + SM_VTLO);
    float* pks = (float*)(smc + SM_PK);

    const int tid = threadIdx.x;
    const int w = tid >> 5, lane = tid & 31;
    const int qr = lane >> 2, qc = lane & 3;
    const int q0 = blockIdx.x * 128;
    const int bh = blockIdx.y;
    const int bi = bh >> 3, head = bh & 7;

    const __nv_bfloat16* qbh = g_qh + (size_t)bh * NN * DD + (size_t)q0 * 64;
    const __nv_bfloat16* qbl = g_ql + (size_t)bh * NN * DD + (size_t)q0 * 64;
    const __nv_bfloat16* kbh = g_kh + (size_t)bh * NN * DD;
    const __nv_bfloat16* kbl = g_kl + (size_t)bh * NN * DD;
    const __nv_bfloat16* vbh = g_vth + (size_t)bh * DD * NN;
    const __nv_bfloat16* vbl = g_vtl + (size_t)bh * DD * NN;

    // Q tiles: 1024 16B-chunks each
#pragma unroll
    for (int s = 0; s < 4; s++) {
        int idx = tid + 256 * s;
        int r = idx >> 3, seg = (idx & 7) * 8;
        *(uint4*)&Qhi[r * QS + seg] = *(const uint4*)&qbh[(size_t)r * 64 + seg];
        *(uint4*)&Qlo[r * QS + seg] = *(const uint4*)&qbl[(size_t)r * 64 + seg];
    }

    const int lrow0 = w * 16 + qr;
    float pqx0 = pos[(q0 + lrow0) * 2 + 0], pqy0 = pos[(q0 + lrow0) * 2 + 1];
    float pqx1 = pos[(q0 + lrow0 + 8) * 2 + 0], pqy1 = pos[(q0 + lrow0 + 8) * 2 + 1];

    float oacc[8][4];
#pragma unroll
    for (int i = 0; i < 8; i++)
#pragma unroll
        for (int j = 0; j < 4; j++) oacc[i][j] = 0.f;
    float lsum0 = 0.f, lsum1 = 0.f;
    float sacc[8][4];

    for (int kt = 0; kt < 32; kt++) {
        const int k0 = kt * 64;
        __syncthreads();
#pragma unroll
        for (int s = 0; s < 2; s++) {
            int idx = tid + 256 * s;
            int r = idx >> 3, seg = (idx & 7) * 8;
            *(uint4*)&Khi[r * QS + seg]  = *(const uint4*)&kbh[(size_t)(k0 + r) * 64 + seg];
            *(uint4*)&Klo[r * QS + seg]  = *(const uint4*)&kbl[(size_t)(k0 + r) * 64 + seg];
            *(uint4*)&Vthi[r * QS + seg] = *(const uint4*)&vbh[(size_t)r * NN + k0 + seg];
            *(uint4*)&Vtlo[r * QS + seg] = *(const uint4*)&vbl[(size_t)r * NN + k0 + seg];
        }
        if (tid < 64)
            *(float2*)&pks[tid * 2] = *(const float2*)(pos + (size_t)(k0 + tid) * 2);
        __syncthreads();

        // ---- S = Q K^T ----
#pragma unroll
        for (int i = 0; i < 8; i++)
#pragma unroll
            for (int j = 0; j < 4; j++) sacc[i][j] = 0.f;

#pragma unroll
        for (int ks = 0; ks < 4; ks++) {
            int abase = lrow0 * QS + ks * 16 + 2 * qc;
            u32 qh0 = *(u32*)&Qhi[abase];
            u32 qh1 = *(u32*)&Qhi[abase + 8 * QS];
            u32 qh2 = *(u32*)&Qhi[abase + 8];
            u32 qh3 = *(u32*)&Qhi[abase + 8 * QS + 8];
            u32 ql0 = *(u32*)&Qlo[abase];
            u32 ql1 = *(u32*)&Qlo[abase + 8 * QS];
            u32 ql2 = *(u32*)&Qlo[abase + 8];
            u32 ql3 = *(u32*)&Qlo[abase + 8 * QS + 8];
#pragma unroll
            for (int nt = 0; nt < 8; nt++) {
                int bbase = (nt * 8 + qr) * QS + ks * 16 + 2 * qc;
                u32 kh0 = *(u32*)&Khi[bbase];
                u32 kh1 = *(u32*)&Khi[bbase + 8];
                u32 kl0 = *(u32*)&Klo[bbase];
                u32 kl1 = *(u32*)&Klo[bbase + 8];
                mma16816(sacc[nt], qh0, qh1, qh2, qh3, kh0, kh1);
                mma16816(sacc[nt], qh0, qh1, qh2, qh3, kl0, kl1);
                mma16816(sacc[nt], ql0, ql1, ql2, ql3, kh0, kh1);
            }
        }

        // ---- softmax (fixed max 8) ----
#pragma unroll
        for (int nt = 0; nt < 8; nt++) {
            int cb = nt * 8 + 2 * qc;
            float4 pk4 = *(const float4*)&pks[cb * 2];
            float dx, dy, e0, e1;
            dx = fabsf(pqx0 - pk4.x); dx = fminf(dx, 1.0f - dx);
            dy = fabsf(pqy0 - pk4.y); dy = fminf(dy, 1.0f - dy);
            e0 = dx * dx + dy * dy;
            dx = fabsf(pqx0 - pk4.z); dx = fminf(dx, 1.0f - dx);
            dy = fabsf(pqy0 - pk4.w); dy = fminf(dy, 1.0f - dy);
            e1 = dx * dx + dy * dy;
            float p0 = exp2f(fmaf(fmaf(sacc[nt][0], 0.125f, -e0), 1.44269504f, -11.54156036f));
            float p1 = exp2f(fmaf(fmaf(sacc[nt][1], 0.125f, -e1), 1.44269504f, -11.54156036f));
            dx = fabsf(pqx1 - pk4.x); dx = fminf(dx, 1.0f - dx);
            dy = fabsf(pqy1 - pk4.y); dy = fminf(dy, 1.0f - dy);
            e0 = dx * dx + dy * dy;
            dx = fabsf(pqx1 - pk4.z); dx = fminf(dx, 1.0f - dx);
            dy = fabsf(pqy1 - pk4.w); dy = fminf(dy, 1.0f - dy);
            e1 = dx * dx + dy * dy;
            float p2 = exp2f(fmaf(fmaf(sacc[nt][2], 0.125f, -e0), 1.44269504f, -11.54156036f));
            float p3 = exp2f(fmaf(fmaf(sacc[nt][3], 0.125f, -e1), 1.44269504f, -11.54156036f));
            lsum0 += p0 + p1;
            lsum1 += p2 + p3;
            sacc[nt][0] = p0; sacc[nt][1] = p1; sacc[nt][2] = p2; sacc[nt][3] = p3;
        }

        // ---- O += P V ----
#pragma unroll
        for (int ks = 0; ks < 4; ks++) {
            u32 ah0 = pack_hi2(sacc[2 * ks][0],     sacc[2 * ks][1]);
            u32 ah1 = pack_hi2(sacc[2 * ks][2],     sacc[2 * ks][3]);
            u32 ah2 = pack_hi2(sacc[2 * ks + 1][0], sacc[2 * ks + 1][1]);
            u32 ah3 = pack_hi2(sacc[2 * ks + 1][2], sacc[2 * ks + 1][3]);
            u32 al0 = pack_lo2(sacc[2 * ks][0],     sacc[2 * ks][1]);
            u32 al1 = pack_lo2(sacc[2 * ks][2],     sacc[2 * ks][3]);
            u32 al2 = pack_lo2(sacc[2 * ks + 1][0], sacc[2 * ks + 1][1]);
            u32 al3 = pack_lo2(sacc[2 * ks + 1][2], sacc[2 * ks + 1][3]);
#pragma unroll
            for (int nt = 0; nt < 8; nt++) {
                int bbase = (nt * 8 + qr) * QS + ks * 16 + 2 * qc;
                u32 vh0 = *(u32*)&Vthi[bbase];
                u32 vh1 = *(u32*)&Vthi[bbase + 8];
                u32 vl0 = *(u32*)&Vtlo[bbase];
                u32 vl1 = *(u32*)&Vtlo[bbase + 8];
                mma16816(oacc[nt], ah0, ah1, ah2, ah3, vh0, vh1);
                mma16816(oacc[nt], ah0, ah1, ah2, ah3, vl0, vl1);
                mma16816(oacc[nt], al0, al1, al2, al3, vh0, vh1);
            }
        }
    }

#pragma unroll
    for (int off = 1; off <= 2; off <<= 1) {
        lsum0 += __shfl_xor_sync(0xffffffffu, lsum0, off);
        lsum1 += __shfl_xor_sync(0xffffffffu, lsum1, off);
    }
    float inv0 = 1.0f / lsum0, inv1 = 1.0f / lsum1;

    __nv_bfloat16* obh = g_atth + ((size_t)bi * NN + q0) * DIM + head * 64;
    __nv_bfloat16* obl = g_attl + ((size_t)bi * NN + q0) * DIM + head * 64;
#pragma unroll
    for (int nt = 0; nt < 8; nt++) {
        int cb = nt * 8 + 2 * qc;
        float a0 = oacc[nt][0] * inv0, a1 = oacc[nt][1] * inv0;
        float b0 = oacc[nt][2] * inv1, b1 = oacc[nt][3] * inv1;
        *(u32*)&obh[(size_t)lrow0 * DIM + cb]       = pack_hi2(a0, a1);
        *(u32*)&obl[(size_t)lrow0 * DIM + cb]       = pack_lo2(a0, a1);
        *(u32*)&obh[(size_t)(lrow0 + 8) * DIM + cb] = pack_hi2(b0, b1);
        *(u32*)&obl[(size_t)(lrow0 + 8) * DIM + cb] = pack_lo2(b0, b1);
    }
}

// ---------------------------------------------------------------------------
// Kernel: output GEMM
// ---------------------------------------------------------------------------
__global__ __launch_bounds__(256, 2) void out_gemm_kernel(
    const float* __restrict__ bout, float* __restrict__ out)
{
    extern __shared__ char smc[];
    const int row0 = blockIdx.y * 128;
    const int col0 = blockIdx.x * 128;
    const int lane = threadIdx.x & 31;
    const int w = threadIdx.x >> 5;
    const int qr = lane >> 2, qc = lane & 3;
    const int wm = w >> 2, wn = w & 3;

    float cacc[4][4][4];
    gemm_mma_body_bf16(g_atth + (size_t)row0 * 512, g_attl + (size_t)row0 * 512,
                       g_wouth + (size_t)col0 * 512, g_woutl + (size_t)col0 * 512,
                       smc, cacc);

#pragma unroll
    for (int mt = 0; mt < 4; mt++) {
        int grow = row0 + wm * 64 + mt * 16 + qr;
#pragma unroll
        for (int nt = 0; nt < 4; nt++) {
            int c0 = col0 + wn * 32 + nt * 8 + 2 * qc;
            float2 bv = *(const float2*)(bout + c0);
            float2 r0 = make_float2(cacc[mt][nt][0] + bv.x, cacc[mt][nt][1] + bv.y);
            float2 r1 = make_float2(cacc[mt][nt][2] + bv.x, cacc[mt][nt][3] + bv.y);
            *(float2*)&out[(size_t)grow * 512 + c0] = r0;
            *(float2*)&out[(size_t)(grow + 8) * 512 + c0] = r1;
        }
    }
}

// ---------------------------------------------------------------------------
extern "C" void kernel_launch(void* const* d_in, const int* in_sizes, int n_in,
                              void* d_out, int out_size)
{
    const float* x    = (const float*)d_in[0];
    const float* pos  = (const float*)d_in[1];
    const float* W_in = (const float*)d_in[2];
    const float* b_in = (const float*)d_in[3];
    const float* qn_w = (const float*)d_in[4];
    const float* qn_b = (const float*)d_in[5];
    const float* kn_w = (const float*)d_in[6];
    const float* kn_b = (const float*)d_in[7];
    const float* W_out= (const float*)d_in[8];
    const float* b_out= (const float*)d_in[9];
    float* out = (float*)d_out;

    cudaFuncSetAttribute(qkv_gemm_kernel, cudaFuncAttributeMaxDynamicSharedMemorySize, GEMM_SMEM_BYTES);
    cudaFuncSetAttribute(out_gemm_kernel, cudaFuncAttributeMaxDynamicSharedMemorySize, GEMM_SMEM_BYTES);
    cudaFuncSetAttribute(attn_kernel, cudaFuncAttributeMaxDynamicSharedMemorySize, ATTN_SMEM_BYTES);

    __nv_bfloat16 *winh, *winl, *wouth, *woutl;
    cudaGetSymbolAddress((void**)&winh, g_winh);
    cudaGetSymbolAddress((void**)&winl, g_winl);
    cudaGetSymbolAddress((void**)&wouth, g_wouth);
    cudaGetSymbolAddress((void**)&woutl, g_woutl);

    prep_x_kernel<<<BN * DIM / 4 / 256, 256>>>(x);
    prep_wt_kernel<<<dim3(1536 / 32, 512 / 32), dim3(32, 8)>>>(W_in, winh, winl, 1536);
    prep_wt_kernel<<<dim3(512 / 32, 512 / 32), dim3(32, 8)>>>(W_out, wouth, woutl, 512);

    qkv_gemm_kernel<<<dim3(12, 32), 256, GEMM_SMEM_BYTES>>>(b_in);
    ln_qk_kernel<<<(2 * BHD * NN) / 8, 256>>>(qn_w, qn_b, kn_w, kn_b);
    vt_kernel<<<dim3(NN / 64, BHD), 256>>>();
    attn_kernel<<<dim3(16, 16), 256, ATTN_SMEM_BYTES>>>(pos);
    out_gemm_kernel<<<dim3(4, 32), 256, GEMM_SMEM_BYTES>>>(b_out, out);
}